// round 7
// baseline (speedup 1.0000x reference)
#include <cuda_runtime.h>
#include <cuda_bf16.h>
#include <cstdint>

#define T_TOKENS 4096
#define H_DIM    2048
#define I_DIM    1408
#define E_NUM    16
#define SI_DIM   2816
#define SLOTS    8192   // T * TOP_K

// ---------------- scratch (device globals; no runtime allocation) ----------
__device__ int   g_cnt[E_NUM];
__device__ int   g_off[E_NUM];
__device__ int   g_cur[E_NUM];
__device__ int   g_eid[T_TOKENS * 2];
__device__ float g_wgt[T_TOKENS * 2];
__device__ int   g_slot[T_TOKENS * 2];
__device__ int   g_rowtok[SLOTS];

// int8 two-term operands for gate/up GEMMs (A = x, B = wg/wu/sg/su)
__device__ int8_t g_xq1[T_TOKENS * H_DIM];
__device__ int8_t g_xq2[T_TOKENS * H_DIM];
__device__ float  g_sx[T_TOKENS];
__device__ int8_t g_wgq1[E_NUM * I_DIM * H_DIM];
__device__ int8_t g_wgq2[E_NUM * I_DIM * H_DIM];
__device__ int8_t g_wuq1[E_NUM * I_DIM * H_DIM];
__device__ int8_t g_wuq2[E_NUM * I_DIM * H_DIM];
__device__ float  g_swg[E_NUM * I_DIM];
__device__ float  g_swu[E_NUM * I_DIM];
__device__ int8_t g_sgq1[SI_DIM * H_DIM];
__device__ int8_t g_sgq2[SI_DIM * H_DIM];
__device__ int8_t g_suq1[SI_DIM * H_DIM];
__device__ int8_t g_suq2[SI_DIM * H_DIM];
__device__ float  g_ssg[SI_DIM];
__device__ float  g_ssu[SI_DIM];

// bf16 hi/lo for down GEMMs
__device__ __nv_bfloat16 g_wdh[E_NUM * H_DIM * I_DIM];   // w_down^T [E][H][I]
__device__ __nv_bfloat16 g_wdl[E_NUM * H_DIM * I_DIM];
__device__ __nv_bfloat16 g_sdh[H_DIM * SI_DIM];          // sd^T [H][SI]
__device__ __nv_bfloat16 g_sdl[H_DIM * SI_DIM];
__device__ __nv_bfloat16 g_hrh[SLOTS * I_DIM];           // routed swiglu acts
__device__ __nv_bfloat16 g_hrl[SLOTS * I_DIM];
__device__ __nv_bfloat16 g_hsh[T_TOKENS * SI_DIM];       // shared swiglu acts
__device__ __nv_bfloat16 g_hsl[T_TOKENS * SI_DIM];
// time-shared fp32 scratch: sharedG -> routedG -> routed Y (16.7M floats)
__device__ float g_Y[SLOTS * H_DIM];

// ---------------- threefry2x32 core (verified vs Random123 KAT) -------------
__device__ __forceinline__ uint32_t rotl32(uint32_t v, int r) {
    return (v << r) | (v >> (32 - r));
}

__device__ __forceinline__ void threefry2x32(uint32_t x0, uint32_t x1,
                                             uint32_t& o0, uint32_t& o1) {
    const uint32_t ks0 = 0u, ks1 = 42u, ks2 = 0u ^ 42u ^ 0x1BD11BDAu;
    x0 += ks0; x1 += ks1;
    x0 += x1; x1 = rotl32(x1, 13); x1 ^= x0;
    x0 += x1; x1 = rotl32(x1, 15); x1 ^= x0;
    x0 += x1; x1 = rotl32(x1, 26); x1 ^= x0;
    x0 += x1; x1 = rotl32(x1, 6);  x1 ^= x0;
    x0 += ks1; x1 += ks2 + 1u;
    x0 += x1; x1 = rotl32(x1, 17); x1 ^= x0;
    x0 += x1; x1 = rotl32(x1, 29); x1 ^= x0;
    x0 += x1; x1 = rotl32(x1, 16); x1 ^= x0;
    x0 += x1; x1 = rotl32(x1, 24); x1 ^= x0;
    x0 += ks2; x1 += ks0 + 2u;
    x0 += x1; x1 = rotl32(x1, 13); x1 ^= x0;
    x0 += x1; x1 = rotl32(x1, 15); x1 ^= x0;
    x0 += x1; x1 = rotl32(x1, 26); x1 ^= x0;
    x0 += x1; x1 = rotl32(x1, 6);  x1 ^= x0;
    x0 += ks0; x1 += ks1 + 3u;
    x0 += x1; x1 = rotl32(x1, 17); x1 ^= x0;
    x0 += x1; x1 = rotl32(x1, 29); x1 ^= x0;
    x0 += x1; x1 = rotl32(x1, 16); x1 ^= x0;
    x0 += x1; x1 = rotl32(x1, 24); x1 ^= x0;
    x0 += ks1; x1 += ks2 + 4u;
    x0 += x1; x1 = rotl32(x1, 13); x1 ^= x0;
    x0 += x1; x1 = rotl32(x1, 15); x1 ^= x0;
    x0 += x1; x1 = rotl32(x1, 26); x1 ^= x0;
    x0 += x1; x1 = rotl32(x1, 6);  x1 ^= x0;
    x0 += ks2; x1 += ks0 + 5u;
    o0 = x0; o1 = x1;
}

__device__ __forceinline__ float erfinv_xla(float x) {
    float w = -log1pf(-x * x);
    float p;
    if (w < 5.0f) {
        w -= 2.5f;
        p = 2.81022636e-08f;
        p = fmaf(p, w, 3.43273939e-07f);
        p = fmaf(p, w, -3.5233877e-06f);
        p = fmaf(p, w, -4.39150654e-06f);
        p = fmaf(p, w, 0.00021858087f);
        p = fmaf(p, w, -0.00125372503f);
        p = fmaf(p, w, -0.00417768164f);
        p = fmaf(p, w, 0.246640727f);
        p = fmaf(p, w, 1.50140941f);
    } else {
        w = sqrtf(w) - 3.0f;
        p = -0.000200214257f;
        p = fmaf(p, w, 0.000100950558f);
        p = fmaf(p, w, 0.00134934322f);
        p = fmaf(p, w, -0.00367342844f);
        p = fmaf(p, w, 0.00573950773f);
        p = fmaf(p, w, -0.0076224613f);
        p = fmaf(p, w, 0.00943887047f);
        p = fmaf(p, w, 1.00167406f);
        p = fmaf(p, w, 2.83297682f);
    }
    return p * x;
}

// ---------------- routing kernels ------------------------------------------
__global__ void zero_kernel() {
    if (threadIdx.x < E_NUM) g_cnt[threadIdx.x] = 0;
}

__global__ void route_kernel() {
    int t = blockIdx.x * blockDim.x + threadIdx.x;
    if (t >= T_TOKENS) return;
    float s[E_NUM];
#pragma unroll
    for (int e = 0; e < E_NUM; ++e) {
        uint32_t i = (uint32_t)t * E_NUM + (uint32_t)e;
        uint32_t o0, o1;
        threefry2x32(0u, i, o0, o1);
        uint32_t bits = o0 ^ o1;
        float u01 = __uint_as_float((bits >> 9) | 0x3f800000u) - 1.0f;
        float u = fmaf(u01, 2.0f, -0.99999994f);
        u = fmaxf(-0.99999994f, u);
        float nz = 1.4142135381698608f * erfinv_xla(u);
        s[e] = 1.0f / (1.0f + expf(-nz));
    }
    int b0 = 0;
#pragma unroll
    for (int e = 1; e < E_NUM; ++e) if (s[e] > s[b0]) b0 = e;
    int b1 = (b0 == 0) ? 1 : 0;
#pragma unroll
    for (int e = 0; e < E_NUM; ++e) if (e != b0 && s[e] > s[b1]) b1 = e;
    float sum = s[b0] + s[b1] + 1e-8f;
    g_eid[2 * t + 0] = b0;
    g_eid[2 * t + 1] = b1;
    g_wgt[2 * t + 0] = s[b0] / sum;
    g_wgt[2 * t + 1] = s[b1] / sum;
    atomicAdd(&g_cnt[b0], 1);
    atomicAdd(&g_cnt[b1], 1);
}

__global__ void scan_kernel() {
    int a = 0;
    for (int e = 0; e < E_NUM; ++e) { g_off[e] = a; g_cur[e] = a; a += g_cnt[e]; }
}

__global__ void scatter_kernel() {
    int t = blockIdx.x * blockDim.x + threadIdx.x;
    if (t >= T_TOKENS) return;
#pragma unroll
    for (int k = 0; k < 2; ++k) {
        int e = g_eid[2 * t + k];
        int sidx = atomicAdd(&g_cur[e], 1);
        g_slot[2 * t + k] = sidx;
        g_rowtok[sidx] = t;
    }
}

// ---------------- quantization / conversion kernels -------------------------
// per-token two-term int8 quantization of x
__global__ void quant_x_kernel(const float* __restrict__ x,
                               int8_t* __restrict__ q1, int8_t* __restrict__ q2,
                               float* __restrict__ Sa) {
    __shared__ float red[256];
    __shared__ float Ssh;
    const int t = threadIdx.x;
    const int tok = blockIdx.x;
    const float* row = x + (size_t)tok * H_DIM;
    float m = 0.f;
    for (int k = t; k < H_DIM; k += 256) m = fmaxf(m, fabsf(row[k]));
    red[t] = m;
    __syncthreads();
    for (int s = 128; s > 0; s >>= 1) {
        if (t < s) red[t] = fmaxf(red[t], red[t + s]);
        __syncthreads();
    }
    if (t == 0) { float S = fmaxf(red[0], 1e-20f) * (1.f / 127.f); Sa[tok] = S; Ssh = S; }
    __syncthreads();
    float inv = 1.f / Ssh;
#pragma unroll
    for (int it = 0; it < 2; ++it) {
        int k4 = (it * 256 + t) * 4;
        float4 v = *(const float4*)(row + k4);
        float vv[4] = {v.x, v.y, v.z, v.w};
        signed char c1[4], c2[4];
#pragma unroll
        for (int j = 0; j < 4; ++j) {
            float f = vv[j] * inv;
            float i1 = rintf(f);
            float i2 = rintf((f - i1) * 128.f);
            c1[j] = (signed char)(int)i1;
            c2[j] = (signed char)(int)i2;
        }
        *(int*)&q1[(size_t)tok * H_DIM + k4] = *(int*)c1;
        *(int*)&q2[(size_t)tok * H_DIM + k4] = *(int*)c2;
    }
}

// per-output-channel max of weight columns: src [z][R][C] -> scale[z][C]
__global__ void colmax_kernel(const float* __restrict__ src,
                              float* __restrict__ scale, int R, int C) {
    __shared__ float red[256];
    size_t zo = (size_t)blockIdx.y * (size_t)R * (size_t)C;
    int c = blockIdx.x * 128 + (threadIdx.x & 127);
    int half = threadIdx.x >> 7;
    float m = 0.f;
    for (int r = half; r < R; r += 2)
        m = fmaxf(m, fabsf(src[zo + (size_t)r * C + c]));
    red[threadIdx.x] = m;
    __syncthreads();
    if (threadIdx.x < 128) {
        float mm = fmaxf(red[threadIdx.x], red[threadIdx.x + 128]);
        scale[(size_t)blockIdx.y * C + blockIdx.x * 128 + threadIdx.x] =
            fmaxf(mm, 1e-20f) * (1.f / 127.f);
    }
}

// transpose + two-term int8 quantize: src [z][R][C] fp32 -> q [z][C][R] int8
__global__ void transpose_quant(const float* __restrict__ src,
                                const float* __restrict__ scale,
                                int8_t* __restrict__ q1, int8_t* __restrict__ q2,
                                int R, int C) {
    __shared__ float tile[32][129];
    size_t zo = (size_t)blockIdx.z * (size_t)R * (size_t)C;
    int c0 = blockIdx.x * 32, r0 = blockIdx.y * 128;
    int t = threadIdx.x;
#pragma unroll
    for (int it = 0; it < 16; ++it) {
        int idx = it * 256 + t;
        int r = idx >> 5, n = idx & 31;
        tile[n][r] = src[zo + (size_t)(r0 + r) * C + c0 + n];
    }
    __syncthreads();
    int n = t >> 3, seg = t & 7;
    float inv = 1.f / scale[(size_t)blockIdx.z * C + c0 + n];
    signed char v1[16], v2[16];
#pragma unroll
    for (int i = 0; i < 16; ++i) {
        float f = tile[n][seg * 16 + i] * inv;
        float i1 = rintf(f);
        float i2 = rintf((f - i1) * 128.f);
        v1[i] = (signed char)(int)i1;
        v2[i] = (signed char)(int)i2;
    }
    size_t ob = zo + (size_t)(c0 + n) * R + r0 + seg * 16;
    *(int4*)(q1 + ob) = *(int4*)v1;
    *(int4*)(q2 + ob) = *(int4*)v2;
}

// transpose + bf16 hi/lo split: src [z][R][C] fp32 -> hi/lo [z][C][R] bf16
__global__ void transpose_bf16hl(const float* __restrict__ src,
                                 __nv_bfloat16* __restrict__ hi,
                                 __nv_bfloat16* __restrict__ lo,
                                 int R, int C) {
    __shared__ float tile[32][129];
    size_t zo = (size_t)blockIdx.z * (size_t)R * (size_t)C;
    int c0 = blockIdx.x * 32, r0 = blockIdx.y * 128;
    int t = threadIdx.x;
#pragma unroll
    for (int it = 0; it < 16; ++it) {
        int idx = it * 256 + t;
        int r = idx >> 5, n = idx & 31;
        tile[n][r] = src[zo + (size_t)(r0 + r) * C + c0 + n];
    }
    __syncthreads();
    int n = t >> 3, seg = t & 7;
    __nv_bfloat16 h[16], l[16];
#pragma unroll
    for (int i = 0; i < 16; ++i) {
        float v = tile[n][seg * 16 + i];
        h[i] = __float2bfloat16(v);
        l[i] = __float2bfloat16(v - __bfloat162float(h[i]));
    }
    size_t ob = zo + (size_t)(c0 + n) * R + r0 + seg * 16;
    *(uint4*)(hi + ob)     = ((uint4*)h)[0];
    *(uint4*)(hi + ob + 8) = ((uint4*)h)[1];
    *(uint4*)(lo + ob)     = ((uint4*)l)[0];
    *(uint4*)(lo + ob + 8) = ((uint4*)l)[1];
}

// ---------------- warp-MMA helpers (portable PTX) ----------------------------
__device__ __forceinline__ uint32_t smem_u32(const void* p) {
    uint32_t a;
    asm("{ .reg .u64 t; cvta.to.shared.u64 t, %1; cvt.u32.u64 %0, t; }"
        : "=r"(a) : "l"(p));
    return a;
}

__device__ __forceinline__ uint32_t swz128(uint32_t off) {
    return off ^ ((off >> 3) & 0x70);
}

__device__ __forceinline__ void cp16(uint32_t s, const void* g) {
    asm volatile("cp.async.cg.shared.global [%0], [%1], 16;"
                 :: "r"(s), "l"(g) : "memory");
}
#define CP_COMMIT() asm volatile("cp.async.commit_group;" ::: "memory")
template <int N>
__device__ __forceinline__ void cp_wait() {
    asm volatile("cp.async.wait_group %0;" :: "n"(N) : "memory");
}

__device__ __forceinline__ void ldsm4(uint32_t* r, uint32_t a) {
    asm volatile("ldmatrix.sync.aligned.m8n8.x4.shared.b16 {%0,%1,%2,%3}, [%4];"
                 : "=r"(r[0]), "=r"(r[1]), "=r"(r[2]), "=r"(r[3]) : "r"(a));
}

__device__ __forceinline__ void mma16816(float* c, const uint32_t* a,
                                         uint32_t b0, uint32_t b1) {
    asm volatile(
        "mma.sync.aligned.m16n8k16.row.col.f32.bf16.bf16.f32 "
        "{%0,%1,%2,%3}, {%4,%5,%6,%7}, {%8,%9}, {%0,%1,%2,%3};"
        : "+f"(c[0]), "+f"(c[1]), "+f"(c[2]), "+f"(c[3])
        : "r"(a[0]), "r"(a[1]), "r"(a[2]), "r"(a[3]), "r"(b0), "r"(b1));
}

__device__ __forceinline__ void imma16832(int* c, const uint32_t* a,
                                          uint32_t b0, uint32_t b1) {
    asm volatile(
        "mma.sync.aligned.m16n8k32.row.col.s32.s8.s8.s32 "
        "{%0,%1,%2,%3}, {%4,%5,%6,%7}, {%8,%9}, {%0,%1,%2,%3};"
        : "+r"(c[0]), "+r"(c[1]), "+r"(c[2]), "+r"(c[3])
        : "r"(a[0]), "r"(a[1]), "r"(a[2]), "r"(a[3]), "r"(b0), "r"(b1));
}

__device__ __forceinline__ float swiglu_f(float g, float u) {
    return (g / (1.0f + expf(-g))) * u;
}

// =============================================================================
// INT8 two-term GEMM (gate/up): C = Sa⊗Sb ∘ ((A1+A2/128)(B1+B2/128)^T approx)
// 3 integer passes: acc1 += A1B1; acc2 += A1B2 + A2B1. (A2B2 dropped.)
// UP=false: write fp32 C. UP=true: read Gf, write bf16 hi/lo of swiglu(G, C).
// CTA 128x128, K-chunk 128 (int8, 128B rows, SW128), 3 stages, 8 warps.
// =============================================================================
#define STAGE_I 65536
template <bool ROUTED, bool GATHER, bool UP>
__global__ void __launch_bounds__(256, 1)
imma_gemm(const int8_t* __restrict__ Aq1, const int8_t* __restrict__ Aq2,
          const float* __restrict__ Sa,
          const int8_t* __restrict__ Bq1, const int8_t* __restrict__ Bq2,
          const float* __restrict__ Sb,
          const float* __restrict__ Gf, float* __restrict__ Cf,
          __nv_bfloat16* __restrict__ Ohi, __nv_bfloat16* __restrict__ Olo,
          int K, int N, int fixedM)
{
    extern __shared__ char smem[];
    const int tid  = threadIdx.x;
    const int wid  = tid >> 5;
    const int lane = tid & 31;

    const int e = blockIdx.z;
    int M, seg;
    if (ROUTED) { M = g_cnt[e]; seg = g_off[e]; }
    else        { M = fixedM;   seg = 0; }
    const int mbase = blockIdx.y * 128;
    if (mbase >= M) return;
    const int nbase = blockIdx.x * 128;

    const uint32_t sb = smem_u32(smem);

    const int lrow = tid >> 1;
    const int hb   = (tid & 1) * 64;
    uint32_t so[4];
#pragma unroll
    for (int j = 0; j < 4; ++j)
        so[j] = swz128((uint32_t)lrow * 128u + (uint32_t)hb + (uint32_t)j * 16u);

    int arow;
    {
        bool v = (mbase + lrow) < M;
        if (ROUTED) {
            int slot = seg + mbase + lrow;
            if (GATHER) arow = v ? g_rowtok[slot] : 0;
            else        arow = v ? slot : seg;
        } else {
            arow = mbase + lrow;
        }
    }
    const size_t bexp = ROUTED ? (size_t)e * (size_t)N * (size_t)K : 0;
    const int brow = nbase + lrow;

    const char* gA1 = (const char*)(Aq1 + (size_t)arow * K) + hb;
    const char* gA2 = (const char*)(Aq2 + (size_t)arow * K) + hb;
    const char* gB1 = (const char*)(Bq1 + bexp + (size_t)brow * K) + hb;
    const char* gB2 = (const char*)(Bq2 + bexp + (size_t)brow * K) + hb;

    const int nk = K >> 7;   // K-chunk 128 int8

#define ISSUE_I(slot, kt)                                                      \
    do {                                                                       \
        uint32_t b_ = sb + (uint32_t)(slot) * STAGE_I;                         \
        size_t ko_ = (size_t)(kt) * 128;                                       \
        _Pragma("unroll")                                                      \
        for (int j_ = 0; j_ < 4; ++j_) {                                       \
            cp16(b_ +         so[j_], gA1 + ko_ + j_ * 16);                    \
            cp16(b_ + 16384 + so[j_], gA2 + ko_ + j_ * 16);                    \
            cp16(b_ + 32768 + so[j_], gB1 + ko_ + j_ * 16);                    \
            cp16(b_ + 49152 + so[j_], gB2 + ko_ + j_ * 16);                    \
        }                                                                      \
        CP_COMMIT();                                                           \
    } while (0)

    const int wm = (wid >> 2) * 64;
    const int wn = (wid & 3) * 32;

    uint32_t aOff[4], bOff[2];
#pragma unroll
    for (int mf = 0; mf < 4; ++mf)
        aOff[mf] = (uint32_t)(wm + mf * 16 + (lane & 15)) * 128u
                 + (uint32_t)((lane >> 4) * 16);
#pragma unroll
    for (int nf2 = 0; nf2 < 2; ++nf2)
        bOff[nf2] = (uint32_t)(wn + nf2 * 16 + (lane & 7) + ((lane & 16) >> 1)) * 128u
                  + (uint32_t)(((lane >> 3) & 1) * 16);

    int acc1[4][4][4], acc2[4][4][4];
#pragma unroll
    for (int i = 0; i < 4; ++i)
#pragma unroll
        for (int j = 0; j < 4; ++j)
#pragma unroll
            for (int q = 0; q < 4; ++q) { acc1[i][j][q] = 0; acc2[i][j][q] = 0; }

    ISSUE_I(0, 0);
    ISSUE_I(1, 1);

    for (int kt = 0; kt < nk; ++kt) {
        const int s = kt % 3;
        if (kt + 1 < nk) cp_wait<1>(); else cp_wait<0>();
        __syncthreads();
        if (kt + 2 < nk) ISSUE_I((kt + 2) % 3, kt + 2);

        const uint32_t stb = sb + (uint32_t)s * STAGE_I;
#pragma unroll
        for (int ks = 0; ks < 4; ++ks) {        // 4 k-steps of 32 int8 (32B)
            const uint32_t kso = (uint32_t)ks * 32u;
            uint32_t a1[4][4], a2[4][4], b1[2][4], b2[2][4];
#pragma unroll
            for (int mf = 0; mf < 4; ++mf) {
                uint32_t off = swz128(aOff[mf] + kso);
                ldsm4(a1[mf], stb + off);
                ldsm4(a2[mf], stb + 16384 + off);
            }
#pragma unroll
            for (int nf2 = 0; nf2 < 2; ++nf2) {
                uint32_t off = swz128(bOff[nf2] + kso);
                ldsm4(b1[nf2], stb + 32768 + off);
                ldsm4(b2[nf2], stb + 49152 + off);
            }
#pragma unroll
            for (int mf = 0; mf < 4; ++mf)
#pragma unroll
                for (int nf = 0; nf < 4; ++nf)
                    imma16832(acc1[mf][nf], a1[mf],
                              b1[nf >> 1][(nf & 1) * 2], b1[nf >> 1][(nf & 1) * 2 + 1]);
#pragma unroll
            for (int mf = 0; mf < 4; ++mf)
#pragma unroll
                for (int nf = 0; nf < 4; ++nf)
                    imma16832(acc2[mf][nf], a1[mf],
                              b2[nf >> 1][(nf & 1) * 2], b2[nf >> 1][(nf & 1) * 2 + 1]);
#pragma unroll
            for (int mf = 0; mf < 4; ++mf)
#pragma unroll
                for (int nf = 0; nf < 4; ++nf)
                    imma16832(acc2[mf][nf], a2[mf],
                              b1[nf >> 1][(nf & 1) * 2], b1[nf >> 1][(nf & 1) * 2 + 1]);
        }
    }
#undef ISSUE_I

    // epilogue
    const size_t rowoff = ROUTED ? (size_t)seg : 0;
    const float* SbBase = Sb + (ROUTED ? (size_t)e * N : 0);
    // per-(mf,h) row scale
    float sav[4][2];
#pragma unroll
    for (int mf = 0; mf < 4; ++mf) {
#pragma unroll
        for (int h = 0; h < 2; ++h) {
            int r = mbase + wm + mf * 16 + (lane >> 2) + h * 8;
            float s = 0.f;
            if (r < M) {
                int tok;
                if (ROUTED) {
                    if (GATHER) tok = g_rowtok[seg + r];
                    else        tok = seg + r;       // not used in practice
                } else tok = r;
                s = Sa[tok];
            }
            sav[mf][h] = s;
        }
    }
#pragma unroll
    for (int mf = 0; mf < 4; ++mf) {
#pragma unroll
        for (int nf = 0; nf < 4; ++nf) {
            int r0 = mbase + wm + mf * 16 + (lane >> 2);
            int n0 = nbase + wn + nf * 8 + (lane & 3) * 2;
            float sb0 = SbBase[n0], sb1 = SbBase[n0 + 1];
            int* c1 = acc1[mf][nf];
            int* c2 = acc2[mf][nf];
#pragma unroll
            for (int h = 0; h < 2; ++h) {
                int r = r0 + h * 8;
                if (r < M) {
                    float sa = sav[mf][h];
                    float f0 = ((float)c1[h * 2 + 0] + (float)c2[h * 2 + 0] * 0.0078125f) * sa * sb0;
                    float f1 = ((float)c1[h * 2 + 1] + (float)c2[h * 2 + 1] * 0.0078125f) * sa * sb1;
                    size_t idx = (rowoff + r) * (size_t)N + n0;
                    if (!UP) {
                        *(float2*)&Cf[idx] = make_float2(f0, f1);
                    } else {
                        float a0 = swiglu_f(Gf[idx], f0);
                        float a1 = swiglu_f(Gf[idx + 1], f1);
                        __nv_bfloat16 h0 = __float2bfloat16(a0);
                        __nv_bfloat16 h1 = __float2bfloat16(a1);
                        __nv_bfloat162 hp = __halves2bfloat162(h0, h1);
                        *(uint32_t*)&Ohi[idx] = *reinterpret_cast<uint32_t*>(&hp);
                        __nv_bfloat16 l0 = __float2bfloat16(a0 - __bfloat162float(h0));
                        __nv_bfloat16 l1 = __float2bfloat16(a1 - __bfloat162float(h1));
                        __nv_bfloat162 lp = __halves2bfloat162(l0, l1);
                        *(uint32_t*)&Olo[idx] = *reinterpret_cast<uint32_t*>(&lp);
                    }
                }
            }
        }
    }
}

// =============================================================================
// DOWN GEMM (bf16 3-pass): C = A@B^T fp32. CTA 128x128, K-chunk 64, 3 stages.
// =============================================================================
#define STAGE_D 65536
template <bool ROUTED>
__global__ void __launch_bounds__(256, 1)
mma_down(const __nv_bfloat16* __restrict__ Ahi, const __nv_bfloat16* __restrict__ Alo,
         const __nv_bfloat16* __restrict__ Bhi, const __nv_bfloat16* __restrict__ Blo,
         float* __restrict__ Cf, int K, int N, int fixedM)
{
    extern __shared__ char smem[];
    const int tid  = threadIdx.x;
    const int wid  = tid >> 5;
    const int lane = tid & 31;

    const int e = blockIdx.z;
    int M, seg;
    if (ROUTED) { M = g_cnt[e]; seg = g_off[e]; }
    else        { M = fixedM;   seg = 0; }
    const int mbase = blockIdx.y * 128;
    if (mbase >= M) return;
    const int nbase = blockIdx.x * 128;

    const uint32_t sb = smem_u32(smem);

    const int lrow = tid >> 1;
    const int hb   = (tid & 1) * 64;
    uint32_t so[4];
#pragma unroll
    for (int j = 0; j < 4; ++j)
        so[j] = swz128((uint32_t)lrow * 128u + (uint32_t)hb + (uint32_t)j * 16u);

    int arow;
    {
        bool v = (mbase + lrow) < M;
        if (ROUTED) arow = v ? (seg + mbase + lrow) : seg;
        else        arow = mbase + lrow;
    }
    const size_t bexp = ROUTED ? (size_t)e * (size_t)N * (size_t)K : 0;
    const int brow = nbase + lrow;

    const char* gAh = (const char*)(Ahi + (size_t)arow * K) + hb;
    const char* gAl = (const char*)(Alo + (size_t)arow * K) + hb;
    const char* gBh = (const char*)(Bhi + bexp + (size_t)brow * K) + hb;
    const char* gBl = (const char*)(Blo + bexp + (size_t)brow * K) + hb;

    const int nk = K >> 6;

#define ISSUE_D(slot, kt)                                                      \
    do {                                                                       \
        uint32_t b_ = sb + (uint32_t)(slot) * STAGE_D;                         \
        size_t ko_ = (size_t)(kt) * 128;                                       \
        _Pragma("unroll")                                                      \
        for (int j_ = 0; j_ < 4; ++j_) {                                       \
            cp16(b_ +         so[j_], gAh + ko_ + j_ * 16);                    \
            cp16(b_ + 16384 + so[j_], gAl + ko_ + j_ * 16);                    \
            cp16(b_ + 32768 + so[j_], gBh + ko_ + j_ * 16);                    \
            cp16(b_ + 49152 + so[j_], gBl + ko_ + j_ * 16);                    \
        }                                                                      \
        CP_COMMIT();                                                           \
    } while (0)

    const int wm = (wid >> 2) * 64;
    const int wn = (wid & 3) * 32;

    uint32_t aOff[4], bOff[2];
#pragma unroll
    for (int mf = 0; mf < 4; ++mf)
        aOff[mf] = (uint32_t)(wm + mf * 16 + (lane & 15)) * 128u
                 + (uint32_t)((lane >> 4) * 16);
#pragma unroll
    for (int nf2 = 0; nf2 < 2; ++nf2)
        bOff[nf2] = (uint32_t)(wn + nf2 * 16 + (lane & 7) + ((lane & 16) >> 1)) * 128u
                  + (uint32_t)(((lane >> 3) & 1) * 16);

    float acc[4][4][4];
#pragma unroll
    for (int i = 0; i < 4; ++i)
#pragma unroll
        for (int j = 0; j < 4; ++j)
#pragma unroll
            for (int q = 0; q < 4; ++q) acc[i][j][q] = 0.0f;

    ISSUE_D(0, 0);
    ISSUE_D(1, 1);

    for (int kt = 0; kt < nk; ++kt) {
        const int s = kt % 3;
        if (kt + 1 < nk) cp_wait<1>(); else cp_wait<0>();
        __syncthreads();
        if (kt + 2 < nk) ISSUE_D((kt + 2) % 3, kt + 2);

        const uint32_t stb = sb + (uint32_t)s * STAGE_D;
#pragma unroll
        for (int ks = 0; ks < 4; ++ks) {
            const uint32_t kso = (uint32_t)ks * 32u;
            uint32_t ah[4][4], al[4][4], bh[2][4], bl[2][4];
#pragma unroll
            for (int mf = 0; mf < 4; ++mf) {
                uint32_t off = swz128(aOff[mf] + kso);
                ldsm4(ah[mf], stb + off);
                ldsm4(al[mf], stb + 16384 + off);
            }
#pragma unroll
            for (int nf2 = 0; nf2 < 2; ++nf2) {
                uint32_t off = swz128(bOff[nf2] + kso);
                ldsm4(bh[nf2], stb + 32768 + off);
                ldsm4(bl[nf2], stb + 49152 + off);
            }
#pragma unroll
            for (int mf = 0; mf < 4; ++mf)
#pragma unroll
                for (int nf = 0; nf < 4; ++nf)
                    mma16816(acc[mf][nf], ah[mf],
                             bh[nf >> 1][(nf & 1) * 2], bh[nf >> 1][(nf & 1) * 2 + 1]);
#pragma unroll
            for (int mf = 0; mf < 4; ++mf)
#pragma unroll
                for (int nf = 0; nf < 4; ++nf)
                    mma16816(acc[mf][nf], al[mf],
                             bh[nf >> 1][(nf & 1) * 2], bh[nf >> 1][(nf & 1) * 2 + 1]);
#pragma unroll
            for (int mf = 0; mf < 4; ++mf)
#pragma unroll
                for (int nf = 0; nf < 4; ++nf)
                    mma16816(acc[mf][nf], ah[mf],
                             bl[nf >> 1][(nf & 1) * 2], bl[nf >> 1][(nf & 1) * 2 + 1]);
        }
    }
#undef ISSUE_D

    const size_t rowoff = ROUTED ? (size_t)seg : 0;
#pragma unroll
    for (int mf = 0; mf < 4; ++mf) {
#pragma unroll
        for (int nf = 0; nf < 4; ++nf) {
            int r0 = mbase + wm + mf * 16 + (lane >> 2);
            int n0 = nbase + wn + nf * 8 + (lane & 3) * 2;
            float* c = acc[mf][nf];
            if (r0 < M)
                *(float2*)&Cf[(rowoff + r0) * (size_t)N + n0] = make_float2(c[0], c[1]);
            if (r0 + 8 < M)
                *(float2*)&Cf[(rowoff + r0 + 8) * (size_t)N + n0] = make_float2(c[2], c[3]);
        }
    }
}

// ---------------- combine: out += w0*Y[slot0] + w1*Y[slot1] ------------------
__global__ void combine_kernel(float* __restrict__ out) {
    int t = blockIdx.y;
    int c = (blockIdx.x * blockDim.x + threadIdx.x) * 4;
    int s0 = g_slot[2 * t + 0], s1 = g_slot[2 * t + 1];
    float w0 = g_wgt[2 * t + 0], w1 = g_wgt[2 * t + 1];
    const float4 y0 = *(const float4*)&g_Y[(size_t)s0 * H_DIM + c];
    const float4 y1 = *(const float4*)&g_Y[(size_t)s1 * H_DIM + c];
    float4 o = *(float4*)&out[(size_t)t * H_DIM + c];
    o.x += w0 * y0.x + w1 * y1.x;
    o.y += w0 * y0.y + w1 * y1.y;
    o.z += w0 * y0.z + w1 * y1.z;
    o.w += w0 * y0.w + w1 * y1.w;
    *(float4*)&out[(size_t)t * H_DIM + c] = o;
}

// ---------------- launch -----------------------------------------------------
extern "C" void kernel_launch(void* const* d_in, const int* in_sizes, int n_in,
                              void* d_out, int out_size) {
    (void)in_sizes; (void)n_in; (void)out_size;
    const float* x      = (const float*)d_in[0];
    // d_in[1] router_w, d_in[2] router_b: dead inputs (RandomSTE forward = noise)
    const float* w_gate = (const float*)d_in[3];
    const float* w_up   = (const float*)d_in[4];
    const float* w_down = (const float*)d_in[5];
    const float* sg     = (const float*)d_in[6];
    const float* su     = (const float*)d_in[7];
    const float* sd     = (const float*)d_in[8];
    float* out = (float*)d_out;

    auto sym = [](const void* s) {
        void* p = nullptr;
        cudaGetSymbolAddress(&p, s);
        return p;
    };
    int8_t* xq1 = (int8_t*)sym(g_xq1);
    int8_t* xq2 = (int8_t*)sym(g_xq2);
    float*  sx  = (float*)sym(g_sx);
    int8_t* wgq1 = (int8_t*)sym(g_wgq1);
    int8_t* wgq2 = (int8_t*)sym(g_wgq2);
    int8_t* wuq1 = (int8_t*)sym(g_wuq1);
    int8_t* wuq2 = (int8_t*)sym(g_wuq2);
    float*  swg  = (float*)sym(g_swg);
    float*  swu  = (float*)sym(g_swu);
    int8_t* sgq1 = (int8_t*)sym(g_sgq1);
    int8_t* sgq2 = (int8_t*)sym(g_sgq2);
    int8_t* suq1 = (int8_t*)sym(g_suq1);
    int8_t* suq2 = (int8_t*)sym(g_suq2);
    float*  ssg  = (float*)sym(g_ssg);
    float*  ssu  = (float*)sym(g_ssu);
    __nv_bfloat16* wdh = (__nv_bfloat16*)sym(g_wdh);
    __nv_bfloat16* wdl = (__nv_bfloat16*)sym(g_wdl);
    __nv_bfloat16* sdh = (__nv_bfloat16*)sym(g_sdh);
    __nv_bfloat16* sdl = (__nv_bfloat16*)sym(g_sdl);
    __nv_bfloat16* hrh = (__nv_bfloat16*)sym(g_hrh);
    __nv_bfloat16* hrl = (__nv_bfloat16*)sym(g_hrl);
    __nv_bfloat16* hsh = (__nv_bfloat16*)sym(g_hsh);
    __nv_bfloat16* hsl = (__nv_bfloat16*)sym(g_hsl);
    float*         Yp  = (float*)sym(g_Y);

    const int SMI = 3 * STAGE_I;   // 196608
    const int SMD = 3 * STAGE_D;   // 196608
    cudaFuncSetAttribute(imma_gemm<false, false, false>,
                         cudaFuncAttributeMaxDynamicSharedMemorySize, SMI);
    cudaFuncSetAttribute(imma_gemm<false, false, true>,
                         cudaFuncAttributeMaxDynamicSharedMemorySize, SMI);
    cudaFuncSetAttribute(imma_gemm<true, true, false>,
                         cudaFuncAttributeMaxDynamicSharedMemorySize, SMI);
    cudaFuncSetAttribute(imma_gemm<true, true, true>,
                         cudaFuncAttributeMaxDynamicSharedMemorySize, SMI);
    cudaFuncSetAttribute(mma_down<false>,
                         cudaFuncAttributeMaxDynamicSharedMemorySize, SMD);
    cudaFuncSetAttribute(mma_down<true>,
                         cudaFuncAttributeMaxDynamicSharedMemorySize, SMD);

    // --- conversions (shared path first) ---
    quant_x_kernel<<<T_TOKENS, 256>>>(x, xq1, xq2, sx);
    colmax_kernel<<<dim3(SI_DIM / 128, 1), 256>>>(sg, ssg, H_DIM, SI_DIM);
    colmax_kernel<<<dim3(SI_DIM / 128, 1), 256>>>(su, ssu, H_DIM, SI_DIM);
    transpose_quant<<<dim3(SI_DIM / 32, H_DIM / 128, 1), 256>>>(
        sg, ssg, sgq1, sgq2, H_DIM, SI_DIM);
    transpose_quant<<<dim3(SI_DIM / 32, H_DIM / 128, 1), 256>>>(
        su, ssu, suq1, suq2, H_DIM, SI_DIM);

    // --- shared expert gate/up (int8): G -> g_Y, then up+swiglu -> hs ---
    imma_gemm<false, false, false>
        <<<dim3(SI_DIM / 128, T_TOKENS / 128, 1), 256, SMI>>>(
            xq1, xq2, sx, sgq1, sgq2, ssg, nullptr, Yp, nullptr, nullptr,
            H_DIM, SI_DIM, T_TOKENS);
    imma_gemm<false, false, true>
        <<<dim3(SI_DIM / 128, T_TOKENS / 128, 1), 256, SMI>>>(
            xq1, xq2, sx, suq1, suq2, ssu, Yp, nullptr, hsh, hsl,
            H_DIM, SI_DIM, T_TOKENS);

    // --- routing ---
    zero_kernel<<<1, 32>>>();
    route_kernel<<<T_TOKENS / 256, 256>>>();
    scan_kernel<<<1, 1>>>();
    scatter_kernel<<<T_TOKENS / 256, 256>>>();

    // --- expert weight conversions ---
    colmax_kernel<<<dim3(I_DIM / 128, E_NUM), 256>>>(w_gate, swg, H_DIM, I_DIM);
    colmax_kernel<<<dim3(I_DIM / 128, E_NUM), 256>>>(w_up, swu, H_DIM, I_DIM);
    transpose_quant<<<dim3(I_DIM / 32, H_DIM / 128, E_NUM), 256>>>(
        w_gate, swg, wgq1, wgq2, H_DIM, I_DIM);
    transpose_quant<<<dim3(I_DIM / 32, H_DIM / 128, E_NUM), 256>>>(
        w_up, swu, wuq1, wuq2, H_DIM, I_DIM);

    // --- routed gate/up (int8, gathered): G -> g_Y, then up+swiglu -> hr ---
    imma_gemm<true, true, false>
        <<<dim3(I_DIM / 128, SLOTS / 128, E_NUM), 256, SMI>>>(
            xq1, xq2, sx, wgq1, wgq2, swg, nullptr, Yp, nullptr, nullptr,
            H_DIM, I_DIM, 0);
    imma_gemm<true, true, true>
        <<<dim3(I_DIM / 128, SLOTS / 128, E_NUM), 256, SMI>>>(
            xq1, xq2, sx, wuq1, wuq2, swu, Yp, nullptr, hrh, hrl,
            H_DIM, I_DIM, 0);

    // --- down-weight bf16 transposes ---
    transpose_bf16hl<<<dim3(H_DIM / 32, SI_DIM / 128, 1), 256>>>(
        sd, sdh, sdl, SI_DIM, H_DIM);
    transpose_bf16hl<<<dim3(H_DIM / 32, I_DIM / 128, E_NUM), 256>>>(
        w_down, wdh, wdl, I_DIM, H_DIM);

    // --- down projections: shared -> out (overwrite), routed -> Y(g_Y) ---
    mma_down<false>
        <<<dim3(H_DIM / 128, T_TOKENS / 128, 1), 256, SMD>>>(
            hsh, hsl, sdh, sdl, out, SI_DIM, H_DIM, T_TOKENS);
    mma_down<true>
        <<<dim3(H_DIM / 128, SLOTS / 128, E_NUM), 256, SMD>>>(
            hrh, hrl, wdh, wdl, Yp, I_DIM, H_DIM, 0);

    // --- combine ---
    combine_kernel<<<dim3(H_DIM / 1024, T_TOKENS), 256>>>(out);
}

// round 8
// speedup vs baseline: 3.1447x; 3.1447x over previous
#include <cuda_runtime.h>
#include <cuda_bf16.h>
#include <cuda_fp16.h>
#include <cstdint>

#define T_TOKENS 4096
#define H_DIM    2048
#define I_DIM    1408
#define E_NUM    16
#define SI_DIM   2816
#define SLOTS    8192   // T * TOP_K

// ---------------- scratch (device globals; no runtime allocation) ----------
__device__ int   g_cnt[E_NUM];
__device__ int   g_off[E_NUM];
__device__ int   g_cur[E_NUM];
__device__ int   g_eid[T_TOKENS * 2];
__device__ float g_wgt[T_TOKENS * 2];
__device__ int   g_slot[T_TOKENS * 2];
__device__ int   g_rowtok[SLOTS];

// activations
__device__ __nv_bfloat16 g_xh[T_TOKENS * H_DIM];   // x bf16 hi (shared path)
__device__ __nv_bfloat16 g_xl[T_TOKENS * H_DIM];   // x bf16 lo
__device__ __half        g_xf[T_TOKENS * H_DIM];   // x fp16 (routed path)
// shared weights, NATURAL layout (no transpose), bf16 hi/lo
__device__ __nv_bfloat16 g_sgh[H_DIM * SI_DIM], g_sgl[H_DIM * SI_DIM];
__device__ __nv_bfloat16 g_suh[H_DIM * SI_DIM], g_sul[H_DIM * SI_DIM];
__device__ __nv_bfloat16 g_sdh[SI_DIM * H_DIM], g_sdl[SI_DIM * H_DIM];
// routed weights, NATURAL layout, fp16 single
__device__ __half g_wgf[E_NUM * H_DIM * I_DIM];
__device__ __half g_wuf[E_NUM * H_DIM * I_DIM];
__device__ __half g_wdf[E_NUM * I_DIM * H_DIM];
// intermediate activations
__device__ __nv_bfloat16 g_hsh[T_TOKENS * SI_DIM], g_hsl[T_TOKENS * SI_DIM];
__device__ __half        g_hrf[SLOTS * I_DIM];
__device__ float g_Y[SLOTS * H_DIM];               // routed down output

// ---------------- threefry2x32 core (verified vs Random123 KAT) -------------
__device__ __forceinline__ uint32_t rotl32(uint32_t v, int r) {
    return (v << r) | (v >> (32 - r));
}

__device__ __forceinline__ void threefry2x32(uint32_t x0, uint32_t x1,
                                             uint32_t& o0, uint32_t& o1) {
    const uint32_t ks0 = 0u, ks1 = 42u, ks2 = 0u ^ 42u ^ 0x1BD11BDAu;
    x0 += ks0; x1 += ks1;
    x0 += x1; x1 = rotl32(x1, 13); x1 ^= x0;
    x0 += x1; x1 = rotl32(x1, 15); x1 ^= x0;
    x0 += x1; x1 = rotl32(x1, 26); x1 ^= x0;
    x0 += x1; x1 = rotl32(x1, 6);  x1 ^= x0;
    x0 += ks1; x1 += ks2 + 1u;
    x0 += x1; x1 = rotl32(x1, 17); x1 ^= x0;
    x0 += x1; x1 = rotl32(x1, 29); x1 ^= x0;
    x0 += x1; x1 = rotl32(x1, 16); x1 ^= x0;
    x0 += x1; x1 = rotl32(x1, 24); x1 ^= x0;
    x0 += ks2; x1 += ks0 + 2u;
    x0 += x1; x1 = rotl32(x1, 13); x1 ^= x0;
    x0 += x1; x1 = rotl32(x1, 15); x1 ^= x0;
    x0 += x1; x1 = rotl32(x1, 26); x1 ^= x0;
    x0 += x1; x1 = rotl32(x1, 6);  x1 ^= x0;
    x0 += ks0; x1 += ks1 + 3u;
    x0 += x1; x1 = rotl32(x1, 17); x1 ^= x0;
    x0 += x1; x1 = rotl32(x1, 29); x1 ^= x0;
    x0 += x1; x1 = rotl32(x1, 16); x1 ^= x0;
    x0 += x1; x1 = rotl32(x1, 24); x1 ^= x0;
    x0 += ks1; x1 += ks2 + 4u;
    x0 += x1; x1 = rotl32(x1, 13); x1 ^= x0;
    x0 += x1; x1 = rotl32(x1, 15); x1 ^= x0;
    x0 += x1; x1 = rotl32(x1, 26); x1 ^= x0;
    x0 += x1; x1 = rotl32(x1, 6);  x1 ^= x0;
    x0 += ks2; x1 += ks0 + 5u;
    o0 = x0; o1 = x1;
}

__device__ __forceinline__ float erfinv_xla(float x) {
    float w = -log1pf(-x * x);
    float p;
    if (w < 5.0f) {
        w -= 2.5f;
        p = 2.81022636e-08f;
        p = fmaf(p, w, 3.43273939e-07f);
        p = fmaf(p, w, -3.5233877e-06f);
        p = fmaf(p, w, -4.39150654e-06f);
        p = fmaf(p, w, 0.00021858087f);
        p = fmaf(p, w, -0.00125372503f);
        p = fmaf(p, w, -0.00417768164f);
        p = fmaf(p, w, 0.246640727f);
        p = fmaf(p, w, 1.50140941f);
    } else {
        w = sqrtf(w) - 3.0f;
        p = -0.000200214257f;
        p = fmaf(p, w, 0.000100950558f);
        p = fmaf(p, w, 0.00134934322f);
        p = fmaf(p, w, -0.00367342844f);
        p = fmaf(p, w, 0.00573950773f);
        p = fmaf(p, w, -0.0076224613f);
        p = fmaf(p, w, 0.00943887047f);
        p = fmaf(p, w, 1.00167406f);
        p = fmaf(p, w, 2.83297682f);
    }
    return p * x;
}

// ---------------- routing kernels ------------------------------------------
__global__ void zero_kernel() {
    if (threadIdx.x < E_NUM) g_cnt[threadIdx.x] = 0;
}

__global__ void route_kernel() {
    int t = blockIdx.x * blockDim.x + threadIdx.x;
    if (t >= T_TOKENS) return;
    float s[E_NUM];
#pragma unroll
    for (int e = 0; e < E_NUM; ++e) {
        uint32_t i = (uint32_t)t * E_NUM + (uint32_t)e;
        uint32_t o0, o1;
        threefry2x32(0u, i, o0, o1);
        uint32_t bits = o0 ^ o1;
        float u01 = __uint_as_float((bits >> 9) | 0x3f800000u) - 1.0f;
        float u = fmaf(u01, 2.0f, -0.99999994f);
        u = fmaxf(-0.99999994f, u);
        float nz = 1.4142135381698608f * erfinv_xla(u);
        s[e] = 1.0f / (1.0f + expf(-nz));
    }
    int b0 = 0;
#pragma unroll
    for (int e = 1; e < E_NUM; ++e) if (s[e] > s[b0]) b0 = e;
    int b1 = (b0 == 0) ? 1 : 0;
#pragma unroll
    for (int e = 0; e < E_NUM; ++e) if (e != b0 && s[e] > s[b1]) b1 = e;
    float sum = s[b0] + s[b1] + 1e-8f;
    g_eid[2 * t + 0] = b0;
    g_eid[2 * t + 1] = b1;
    g_wgt[2 * t + 0] = s[b0] / sum;
    g_wgt[2 * t + 1] = s[b1] / sum;
    atomicAdd(&g_cnt[b0], 1);
    atomicAdd(&g_cnt[b1], 1);
}

__global__ void scan_kernel() {
    int a = 0;
    for (int e = 0; e < E_NUM; ++e) { g_off[e] = a; g_cur[e] = a; a += g_cnt[e]; }
}

__global__ void scatter_kernel() {
    int t = blockIdx.x * blockDim.x + threadIdx.x;
    if (t >= T_TOKENS) return;
#pragma unroll
    for (int k = 0; k < 2; ++k) {
        int e = g_eid[2 * t + k];
        int sidx = atomicAdd(&g_cur[e], 1);
        g_slot[2 * t + k] = sidx;
        g_rowtok[sidx] = t;
    }
}

// ---------------- streaming conversion kernels (no transpose) ---------------
__global__ void conv_x(const float* __restrict__ x,
                       __nv_bfloat16* __restrict__ hi,
                       __nv_bfloat16* __restrict__ lo,
                       __half* __restrict__ hf) {
    int i = (blockIdx.x * blockDim.x + threadIdx.x) * 4;
    float4 v = *(const float4*)(x + i);
    float vv[4] = {v.x, v.y, v.z, v.w};
    __nv_bfloat16 h[4], l[4];
    __half f[4];
#pragma unroll
    for (int k = 0; k < 4; ++k) {
        h[k] = __float2bfloat16(vv[k]);
        l[k] = __float2bfloat16(vv[k] - __bfloat162float(h[k]));
        f[k] = __float2half_rn(vv[k]);
    }
    *(uint2*)(hi + i) = *(uint2*)h;
    *(uint2*)(lo + i) = *(uint2*)l;
    *(uint2*)(hf + i) = *(uint2*)f;
}

__global__ void conv_bf16hl(const float* __restrict__ src,
                            __nv_bfloat16* __restrict__ hi,
                            __nv_bfloat16* __restrict__ lo) {
    size_t i = ((size_t)blockIdx.x * blockDim.x + threadIdx.x) * 4;
    float4 v = *(const float4*)(src + i);
    float vv[4] = {v.x, v.y, v.z, v.w};
    __nv_bfloat16 h[4], l[4];
#pragma unroll
    for (int k = 0; k < 4; ++k) {
        h[k] = __float2bfloat16(vv[k]);
        l[k] = __float2bfloat16(vv[k] - __bfloat162float(h[k]));
    }
    *(uint2*)(hi + i) = *(uint2*)h;
    *(uint2*)(lo + i) = *(uint2*)l;
}

__global__ void conv_f16(const float* __restrict__ src,
                         __half* __restrict__ dst) {
    size_t i = ((size_t)blockIdx.x * blockDim.x + threadIdx.x) * 4;
    float4 v = *(const float4*)(src + i);
    float vv[4] = {v.x, v.y, v.z, v.w};
    __half f[4];
#pragma unroll
    for (int k = 0; k < 4; ++k) f[k] = __float2half_rn(vv[k]);
    *(uint2*)(dst + i) = *(uint2*)f;
}

// ---------------- warp-MMA helpers ------------------------------------------
__device__ __forceinline__ uint32_t smem_u32(const void* p) {
    uint32_t a;
    asm("{ .reg .u64 t; cvta.to.shared.u64 t, %1; cvt.u32.u64 %0, t; }"
        : "=r"(a) : "l"(p));
    return a;
}

__device__ __forceinline__ void cp16(uint32_t s, const void* g) {
    asm volatile("cp.async.cg.shared.global [%0], [%1], 16;"
                 :: "r"(s), "l"(g) : "memory");
}
#define CP_COMMIT() asm volatile("cp.async.commit_group;" ::: "memory")
template <int N>
__device__ __forceinline__ void cp_wait() {
    asm volatile("cp.async.wait_group %0;" :: "n"(N) : "memory");
}

__device__ __forceinline__ void ldsm4(uint32_t* r, uint32_t a) {
    asm volatile("ldmatrix.sync.aligned.m8n8.x4.shared.b16 {%0,%1,%2,%3}, [%4];"
                 : "=r"(r[0]), "=r"(r[1]), "=r"(r[2]), "=r"(r[3]) : "r"(a));
}
__device__ __forceinline__ void ldsm4t(uint32_t* r, uint32_t a) {
    asm volatile("ldmatrix.sync.aligned.m8n8.x4.trans.shared.b16 {%0,%1,%2,%3}, [%4];"
                 : "=r"(r[0]), "=r"(r[1]), "=r"(r[2]), "=r"(r[3]) : "r"(a));
}

template <bool HALF>
__device__ __forceinline__ void mma_any(float* c, const uint32_t* a,
                                        uint32_t b0, uint32_t b1) {
    if constexpr (HALF) {
        asm volatile(
            "mma.sync.aligned.m16n8k16.row.col.f32.f16.f16.f32 "
            "{%0,%1,%2,%3}, {%4,%5,%6,%7}, {%8,%9}, {%0,%1,%2,%3};"
            : "+f"(c[0]), "+f"(c[1]), "+f"(c[2]), "+f"(c[3])
            : "r"(a[0]), "r"(a[1]), "r"(a[2]), "r"(a[3]), "r"(b0), "r"(b1));
    } else {
        asm volatile(
            "mma.sync.aligned.m16n8k16.row.col.f32.bf16.bf16.f32 "
            "{%0,%1,%2,%3}, {%4,%5,%6,%7}, {%8,%9}, {%0,%1,%2,%3};"
            : "+f"(c[0]), "+f"(c[1]), "+f"(c[2]), "+f"(c[3])
            : "r"(a[0]), "r"(a[1]), "r"(a[2]), "r"(a[3]), "r"(b0), "r"(b1));
    }
}

__device__ __forceinline__ float swiglu_f(float g, float u) {
    return (g / (1.0f + expf(-g))) * u;
}

// A-tile swizzles (row width W bytes)
template <int W>
__device__ __forceinline__ uint32_t swzA(uint32_t off) {
    return off ^ ((off >> 3) & (W == 128 ? 0x70u : 0x30u));
}

// =============================================================================
// FUSED gate+up GEMM. A k-major [M][K]; B NATURAL [K][N] via ldmatrix.trans.
// TRIPLE: bf16 hi/lo, 3 passes, epilogue -> bf16 hi/lo swiglu acts.
// !TRIPLE: fp16 single pass, epilogue -> fp16 swiglu acts.
// CTA 128x128, 3 stages, 8 warps (2x4), warp tile 64x32.
// =============================================================================
template <bool TRIPLE, bool ROUTED, bool GATHER, bool HALF, int KC>
__global__ void __launch_bounds__(256, 1)
mma_fused(const void* Ah_, const void* Al_,
          const void* B1h_, const void* B1l_,
          const void* B2h_, const void* B2l_,
          __nv_bfloat16* __restrict__ Ohi, __nv_bfloat16* __restrict__ Olo,
          __half* __restrict__ Ohf,
          int K, int N, int fixedM)
{
    constexpr int TILE = KC * 256;
    constexpr int NT   = TRIPLE ? 6 : 3;
    constexpr int STG  = NT * TILE;
    constexpr int W    = KC * 2;       // A row bytes
    constexpr int NJ   = W / 32;       // 16B chunks per thread per tile
    constexpr int KSTEPS = KC / 16;
    constexpr int OF_AL  = TILE;
    constexpr int OF_B1H = (TRIPLE ? 2 : 1) * TILE;
    constexpr int OF_B1L = OF_B1H + TILE;
    constexpr int OF_B2H = (TRIPLE ? 4 : 2) * TILE;
    constexpr int OF_B2L = OF_B2H + TILE;

    extern __shared__ char smem[];
    const int tid  = threadIdx.x;
    const int wid  = tid >> 5;
    const int lane = tid & 31;

    const int e = blockIdx.z;
    int M, seg;
    if (ROUTED) { M = g_cnt[e]; seg = g_off[e]; }
    else        { M = fixedM;   seg = 0; }
    const int mbase = blockIdx.y * 128;
    if (mbase >= M) return;
    const int nbase = blockIdx.x * 128;

    const uint32_t sb = smem_u32(smem);

    // ---- A loader geometry
    const int lrow = tid >> 1;
    const int hbA  = (tid & 1) * (W / 2);
    uint32_t soA[NJ];
#pragma unroll
    for (int j = 0; j < NJ; ++j)
        soA[j] = swzA<W>((uint32_t)lrow * W + (uint32_t)hbA + j * 16u);

    int arow;
    {
        bool v = (mbase + lrow) < M;
        if (ROUTED) {
            int slot = seg + mbase + lrow;
            if (GATHER) arow = v ? g_rowtok[slot] : 0;
            else        arow = v ? slot : seg;
        } else arow = mbase + lrow;
    }
    const char* gAh = (const char*)Ah_ + ((size_t)arow * K) * 2 + hbA;
    const char* gAl = TRIPLE ? (const char*)Al_ + ((size_t)arow * K) * 2 + hbA : nullptr;

    // ---- B loader geometry (tile rows = k, 256B each)
    constexpr int TPR = 256 / KC;          // threads per B row
    const int bk  = tid / TPR;
    const int bnb = (tid % TPR) * (NJ * 16);
    uint32_t soB[NJ];
#pragma unroll
    for (int j = 0; j < NJ; ++j)
        soB[j] = (uint32_t)bk * 256u + (((uint32_t)bnb + j * 16u) ^ (((uint32_t)bk & 7u) << 4));

    const size_t bexp = ROUTED ? (size_t)e * (size_t)K * (size_t)N : 0;
    const size_t brow = bexp + (size_t)bk * N + nbase;
    const char* gB1h = (const char*)B1h_ + brow * 2 + bnb;
    const char* gB1l = TRIPLE ? (const char*)B1l_ + brow * 2 + bnb : nullptr;
    const char* gB2h = (const char*)B2h_ + brow * 2 + bnb;
    const char* gB2l = TRIPLE ? (const char*)B2l_ + brow * 2 + bnb : nullptr;
    const size_t bstep = (size_t)KC * N * 2;

    const int nk = K / KC;

#define ISSUE_F(slot, kt)                                                       \
    do {                                                                        \
        uint32_t b_ = sb + (uint32_t)(slot) * STG;                              \
        size_t ak_ = (size_t)(kt) * W;                                          \
        size_t bk_ = (size_t)(kt) * bstep;                                      \
        _Pragma("unroll")                                                       \
        for (int j_ = 0; j_ < NJ; ++j_) {                                       \
            cp16(b_ + soA[j_], gAh + ak_ + j_ * 16);                            \
            if (TRIPLE) cp16(b_ + OF_AL + soA[j_], gAl + ak_ + j_ * 16);        \
            cp16(b_ + OF_B1H + soB[j_], gB1h + bk_ + j_ * 16);                  \
            if (TRIPLE) cp16(b_ + OF_B1L + soB[j_], gB1l + bk_ + j_ * 16);      \
            cp16(b_ + OF_B2H + soB[j_], gB2h + bk_ + j_ * 16);                  \
            if (TRIPLE) cp16(b_ + OF_B2L + soB[j_], gB2l + bk_ + j_ * 16);      \
        }                                                                       \
        CP_COMMIT();                                                            \
    } while (0)

    const int wm = (wid >> 2) * 64;
    const int wn = (wid & 3) * 32;

    uint32_t aOff[4];
#pragma unroll
    for (int mf = 0; mf < 4; ++mf)
        aOff[mf] = (uint32_t)(wm + mf * 16 + (lane & 15)) * W
                 + (uint32_t)((lane >> 4) * 16);
    // B trans-fragment per-lane base: m=lane>>3 selects (k-half, n-half)
    uint32_t bB[2];
    {
        uint32_t r = lane & 7u, m = lane >> 3;
#pragma unroll
        for (int nf2 = 0; nf2 < 2; ++nf2) {
            uint32_t nb = (uint32_t)(wn + nf2 * 16 + (int)((m >> 1) * 8)) * 2u;
            bB[nf2] = ((m & 1u) * 8u + r) * 256u + (nb ^ (r << 4));
        }
    }

    float accG[4][4][4], accU[4][4][4];
#pragma unroll
    for (int i = 0; i < 4; ++i)
#pragma unroll
        for (int j = 0; j < 4; ++j)
#pragma unroll
            for (int q = 0; q < 4; ++q) { accG[i][j][q] = 0.f; accU[i][j][q] = 0.f; }

    ISSUE_F(0, 0);
    ISSUE_F(1, 1);

    for (int kt = 0; kt < nk; ++kt) {
        const int s = kt % 3;
        if (kt + 1 < nk) cp_wait<1>(); else cp_wait<0>();
        __syncthreads();
        if (kt + 2 < nk) ISSUE_F((kt + 2) % 3, kt + 2);

        const uint32_t stb = sb + (uint32_t)s * STG;
#pragma unroll
        for (int ks = 0; ks < KSTEPS; ++ks) {
            uint32_t ah[4][4], al[4][4], bh[2][4], bl[2][4];
#pragma unroll
            for (int mf = 0; mf < 4; ++mf) {
                uint32_t off = swzA<W>(aOff[mf] + ks * 32u);
                ldsm4(ah[mf], stb + off);
                if (TRIPLE) ldsm4(al[mf], stb + OF_AL + off);
            }
            // ---- gate ----
#pragma unroll
            for (int nf2 = 0; nf2 < 2; ++nf2) {
                uint32_t off = bB[nf2] + ks * 4096u;
                ldsm4t(bh[nf2], stb + OF_B1H + off);
                if (TRIPLE) ldsm4t(bl[nf2], stb + OF_B1L + off);
            }
#pragma unroll
            for (int mf = 0; mf < 4; ++mf)
#pragma unroll
                for (int nf = 0; nf < 4; ++nf)
                    mma_any<HALF>(accG[mf][nf], ah[mf],
                                  bh[nf >> 1][(nf & 1) * 2], bh[nf >> 1][(nf & 1) * 2 + 1]);
            if (TRIPLE) {
#pragma unroll
                for (int mf = 0; mf < 4; ++mf)
#pragma unroll
                    for (int nf = 0; nf < 4; ++nf)
                        mma_any<HALF>(accG[mf][nf], al[mf],
                                      bh[nf >> 1][(nf & 1) * 2], bh[nf >> 1][(nf & 1) * 2 + 1]);
#pragma unroll
                for (int mf = 0; mf < 4; ++mf)
#pragma unroll
                    for (int nf = 0; nf < 4; ++nf)
                        mma_any<HALF>(accG[mf][nf], ah[mf],
                                      bl[nf >> 1][(nf & 1) * 2], bl[nf >> 1][(nf & 1) * 2 + 1]);
            }
            // ---- up ----
#pragma unroll
            for (int nf2 = 0; nf2 < 2; ++nf2) {
                uint32_t off = bB[nf2] + ks * 4096u;
                ldsm4t(bh[nf2], stb + OF_B2H + off);
                if (TRIPLE) ldsm4t(bl[nf2], stb + OF_B2L + off);
            }
#pragma unroll
            for (int mf = 0; mf < 4; ++mf)
#pragma unroll
                for (int nf = 0; nf < 4; ++nf)
                    mma_any<HALF>(accU[mf][nf], ah[mf],
                                  bh[nf >> 1][(nf & 1) * 2], bh[nf >> 1][(nf & 1) * 2 + 1]);
            if (TRIPLE) {
#pragma unroll
                for (int mf = 0; mf < 4; ++mf)
#pragma unroll
                    for (int nf = 0; nf < 4; ++nf)
                        mma_any<HALF>(accU[mf][nf], al[mf],
                                      bh[nf >> 1][(nf & 1) * 2], bh[nf >> 1][(nf & 1) * 2 + 1]);
#pragma unroll
                for (int mf = 0; mf < 4; ++mf)
#pragma unroll
                    for (int nf = 0; nf < 4; ++nf)
                        mma_any<HALF>(accU[mf][nf], ah[mf],
                                      bl[nf >> 1][(nf & 1) * 2], bl[nf >> 1][(nf & 1) * 2 + 1]);
            }
        }
    }
#undef ISSUE_F

    // ---- epilogue: swiglu
    const size_t rowoff = ROUTED ? (size_t)seg : 0;
#pragma unroll
    for (int mf = 0; mf < 4; ++mf) {
#pragma unroll
        for (int nf = 0; nf < 4; ++nf) {
            int r0 = mbase + wm + mf * 16 + (lane >> 2);
            int n0 = nbase + wn + nf * 8 + (lane & 3) * 2;
            float* cg = accG[mf][nf];
            float* cu = accU[mf][nf];
#pragma unroll
            for (int h = 0; h < 2; ++h) {
                int r = r0 + h * 8;
                if (r < M) {
                    size_t idx = (rowoff + r) * (size_t)N + n0;
                    float a0 = swiglu_f(cg[h * 2 + 0], cu[h * 2 + 0]);
                    float a1 = swiglu_f(cg[h * 2 + 1], cu[h * 2 + 1]);
                    if (TRIPLE) {
                        __nv_bfloat16 h0 = __float2bfloat16(a0);
                        __nv_bfloat16 h1 = __float2bfloat16(a1);
                        __nv_bfloat162 hp = __halves2bfloat162(h0, h1);
                        *(uint32_t*)&Ohi[idx] = *reinterpret_cast<uint32_t*>(&hp);
                        __nv_bfloat16 l0 = __float2bfloat16(a0 - __bfloat162float(h0));
                        __nv_bfloat16 l1 = __float2bfloat16(a1 - __bfloat162float(h1));
                        __nv_bfloat162 lp = __halves2bfloat162(l0, l1);
                        *(uint32_t*)&Olo[idx] = *reinterpret_cast<uint32_t*>(&lp);
                    } else {
                        __half2 hp = __floats2half2_rn(a0, a1);
                        *(uint32_t*)&Ohf[idx] = *reinterpret_cast<uint32_t*>(&hp);
                    }
                }
            }
        }
    }
}

// =============================================================================
// DOWN GEMM. A k-major; B NATURAL [K][N] via ldmatrix.trans; out fp32.
// TRIPLE: bf16 3-pass. !TRIPLE: fp16 single pass. KC=64, 3 stages.
// =============================================================================
template <bool TRIPLE, bool ROUTED, bool HALF>
__global__ void __launch_bounds__(256, 1)
mma_down(const void* Ah_, const void* Al_,
         const void* Bh_, const void* Bl_,
         float* __restrict__ Cf, int K, int N, int fixedM)
{
    constexpr int KC = 64;
    constexpr int TILE = KC * 256;     // 16 KB
    constexpr int NT   = TRIPLE ? 4 : 2;
    constexpr int STG  = NT * TILE;
    constexpr int W    = 128;
    constexpr int NJ   = 4;
    constexpr int OF_AL = TILE;
    constexpr int OF_BH = (TRIPLE ? 2 : 1) * TILE;
    constexpr int OF_BL = OF_BH + TILE;

    extern __shared__ char smem[];
    const int tid  = threadIdx.x;
    const int wid  = tid >> 5;
    const int lane = tid & 31;

    const int e = blockIdx.z;
    int M, seg;
    if (ROUTED) { M = g_cnt[e]; seg = g_off[e]; }
    else        { M = fixedM;   seg = 0; }
    const int mbase = blockIdx.y * 128;
    if (mbase >= M) return;
    const int nbase = blockIdx.x * 128;

    const uint32_t sb = smem_u32(smem);

    const int lrow = tid >> 1;
    const int hbA  = (tid & 1) * 64;
    uint32_t soA[NJ];
#pragma unroll
    for (int j = 0; j < NJ; ++j)
        soA[j] = swzA<W>((uint32_t)lrow * 128u + (uint32_t)hbA + j * 16u);

    int arow;
    {
        bool v = (mbase + lrow) < M;
        if (ROUTED) arow = v ? (seg + mbase + lrow) : seg;
        else        arow = mbase + lrow;
    }
    const char* gAh = (const char*)Ah_ + ((size_t)arow * K) * 2 + hbA;
    const char* gAl = TRIPLE ? (const char*)Al_ + ((size_t)arow * K) * 2 + hbA : nullptr;

    const int bk  = tid >> 2;
    const int bnb = (tid & 3) * 64;
    uint32_t soB[NJ];
#pragma unroll
    for (int j = 0; j < NJ; ++j)
        soB[j] = (uint32_t)bk * 256u + (((uint32_t)bnb + j * 16u) ^ (((uint32_t)bk & 7u) << 4));

    const size_t bexp = ROUTED ? (size_t)e * (size_t)K * (size_t)N : 0;
    const size_t brow = bexp + (size_t)bk * N + nbase;
    const char* gBh = (const char*)Bh_ + brow * 2 + bnb;
    const char* gBl = TRIPLE ? (const char*)Bl_ + brow * 2 + bnb : nullptr;
    const size_t bstep = (size_t)KC * N * 2;

    const int nk = K / KC;

#define ISSUE_D(slot, kt)                                                       \
    do {                                                                        \
        uint32_t b_ = sb + (uint32_t)(slot) * STG;                              \
        size_t ak_ = (size_t)(kt) * 128;                                        \
        size_t bk_ = (size_t)(kt) * bstep;                                      \
        _Pragma("unroll")                                                       \
        for (int j_ = 0; j_ < NJ; ++j_) {                                       \
            cp16(b_ + soA[j_], gAh + ak_ + j_ * 16);                            \
            if (TRIPLE) cp16(b_ + OF_AL + soA[j_], gAl + ak_ + j_ * 16);        \
            cp16(b_ + OF_BH + soB[j_], gBh + bk_ + j_ * 16);                    \
            if (TRIPLE) cp16(b_ + OF_BL + soB[j_], gBl + bk_ + j_ * 16);        \
        }                                                                       \
        CP_COMMIT();                                                            \
    } while (0)

    const int wm = (wid >> 2) * 64;
    const int wn = (wid & 3) * 32;

    uint32_t aOff[4];
#pragma unroll
    for (int mf = 0; mf < 4; ++mf)
        aOff[mf] = (uint32_t)(wm + mf * 16 + (lane & 15)) * 128u
                 + (uint32_t)((lane >> 4) * 16);
    uint32_t bB[2];
    {
        uint32_t r = lane & 7u, m = lane >> 3;
#pragma unroll
        for (int nf2 = 0; nf2 < 2; ++nf2) {
            uint32_t nb = (uint32_t)(wn + nf2 * 16 + (int)((m >> 1) * 8)) * 2u;
            bB[nf2] = ((m & 1u) * 8u + r) * 256u + (nb ^ (r << 4));
        }
    }

    float acc[4][4][4];
#pragma unroll
    for (int i = 0; i < 4; ++i)
#pragma unroll
        for (int j = 0; j < 4; ++j)
#pragma unroll
            for (int q = 0; q < 4; ++q) acc[i][j][q] = 0.f;

    ISSUE_D(0, 0);
    ISSUE_D(1, 1);

    for (int kt = 0; kt < nk; ++kt) {
        const int s = kt % 3;
        if (kt + 1 < nk) cp_wait<1>(); else cp_wait<0>();
        __syncthreads();
        if (kt + 2 < nk) ISSUE_D((kt + 2) % 3, kt + 2);

        const uint32_t stb = sb + (uint32_t)s * STG;
#pragma unroll
        for (int ks = 0; ks < 4; ++ks) {
            uint32_t ah[4][4], al[4][4], bh[2][4], bl[2][4];
#pragma unroll
            for (int mf = 0; mf < 4; ++mf) {
                uint32_t off = swzA<W>(aOff[mf] + ks * 32u);
                ldsm4(ah[mf], stb + off);
                if (TRIPLE) ldsm4(al[mf], stb + OF_AL + off);
            }
#pragma unroll
            for (int nf2 = 0; nf2 < 2; ++nf2) {
                uint32_t off = bB[nf2] + ks * 4096u;
                ldsm4t(bh[nf2], stb + OF_BH + off);
                if (TRIPLE) ldsm4t(bl[nf2], stb + OF_BL + off);
            }
#pragma unroll
            for (int mf = 0; mf < 4; ++mf)
#pragma unroll
                for (int nf = 0; nf < 4; ++nf)
                    mma_any<HALF>(acc[mf][nf], ah[mf],
                                  bh[nf >> 1][(nf & 1) * 2], bh[nf >> 1][(nf & 1) * 2 + 1]);
            if (TRIPLE) {
#pragma unroll
                for (int mf = 0; mf < 4; ++mf)
#pragma unroll
                    for (int nf = 0; nf < 4; ++nf)
                        mma_any<HALF>(acc[mf][nf], al[mf],
                                      bh[nf >> 1][(nf & 1) * 2], bh[nf >> 1][(nf & 1) * 2 + 1]);
#pragma unroll
                for (int mf = 0; mf < 4; ++mf)
#pragma unroll
                    for (int nf = 0; nf < 4; ++nf)
                        mma_any<HALF>(acc[mf][nf], ah[mf],
                                      bl[nf >> 1][(nf & 1) * 2], bl[nf >> 1][(nf & 1) * 2 + 1]);
            }
        }
    }
#undef ISSUE_D

    const size_t rowoff = ROUTED ? (size_t)seg : 0;
#pragma unroll
    for (int mf = 0; mf < 4; ++mf) {
#pragma unroll
        for (int nf = 0; nf < 4; ++nf) {
            int r0 = mbase + wm + mf * 16 + (lane >> 2);
            int n0 = nbase + wn + nf * 8 + (lane & 3) * 2;
            float* c = acc[mf][nf];
            if (r0 < M)
                *(float2*)&Cf[(rowoff + r0) * (size_t)N + n0] = make_float2(c[0], c[1]);
            if (r0 + 8 < M)
                *(float2*)&Cf[(rowoff + r0 + 8) * (size_t)N + n0] = make_float2(c[2], c[3]);
        }
    }
}

// ---------------- combine: out += w0*Y[slot0] + w1*Y[slot1] ------------------
__global__ void combine_kernel(float* __restrict__ out) {
    int t = blockIdx.y;
    int c = (blockIdx.x * blockDim.x + threadIdx.x) * 4;
    int s0 = g_slot[2 * t + 0], s1 = g_slot[2 * t + 1];
    float w0 = g_wgt[2 * t + 0], w1 = g_wgt[2 * t + 1];
    const float4 y0 = *(const float4*)&g_Y[(size_t)s0 * H_DIM + c];
    const float4 y1 = *(const float4*)&g_Y[(size_t)s1 * H_DIM + c];
    float4 o = *(float4*)&out[(size_t)t * H_DIM + c];
    o.x += w0 * y0.x + w1 * y1.x;
    o.y += w0 * y0.y + w1 * y1.y;
    o.z += w0 * y0.z + w1 * y1.z;
    o.w += w0 * y0.w + w1 * y1.w;
    *(float4*)&out[(size_t)t * H_DIM + c] = o;
}

// ---------------- launch -----------------------------------------------------
extern "C" void kernel_launch(void* const* d_in, const int* in_sizes, int n_in,
                              void* d_out, int out_size) {
    (void)in_sizes; (void)n_in; (void)out_size;
    const float* x      = (const float*)d_in[0];
    // d_in[1] router_w, d_in[2] router_b: dead inputs (RandomSTE forward = noise)
    const float* w_gate = (const float*)d_in[3];
    const float* w_up   = (const float*)d_in[4];
    const float* w_down = (const float*)d_in[5];
    const float* sg     = (const float*)d_in[6];
    const float* su     = (const float*)d_in[7];
    const float* sd     = (const float*)d_in[8];
    float* out = (float*)d_out;

    auto sym = [](const void* s) {
        void* p = nullptr;
        cudaGetSymbolAddress(&p, s);
        return p;
    };
    __nv_bfloat16* xh  = (__nv_bfloat16*)sym(g_xh);
    __nv_bfloat16* xl  = (__nv_bfloat16*)sym(g_xl);
    __half*        xf  = (__half*)sym(g_xf);
    __nv_bfloat16* sgh = (__nv_bfloat16*)sym(g_sgh);
    __nv_bfloat16* sgl = (__nv_bfloat16*)sym(g_sgl);
    __nv_bfloat16* suh = (__nv_bfloat16*)sym(g_suh);
    __nv_bfloat16* sul = (__nv_bfloat16*)sym(g_sul);
    __nv_bfloat16* sdh = (__nv_bfloat16*)sym(g_sdh);
    __nv_bfloat16* sdl = (__nv_bfloat16*)sym(g_sdl);
    __half* wgf = (__half*)sym(g_wgf);
    __half* wuf = (__half*)sym(g_wuf);
    __half* wdf = (__half*)sym(g_wdf);
    __nv_bfloat16* hsh = (__nv_bfloat16*)sym(g_hsh);
    __nv_bfloat16* hsl = (__nv_bfloat16*)sym(g_hsl);
    __half*        hrf = (__half*)sym(g_hrf);
    float*         Yp  = (float*)sym(g_Y);

    // shared fused: KC=32, 6 tiles/stage -> 48KB * 3 = 144KB
    // routed fused: KC=64, 3 tiles/stage -> 48KB * 3 = 144KB
    // shared down:  4 tiles * 16KB * 3 = 192KB; routed down: 2*16*3 = 96KB
    const int SM_SF = 3 * 6 * (32 * 256);
    const int SM_RF = 3 * 3 * (64 * 256);
    const int SM_SD = 3 * 4 * (64 * 256);
    const int SM_RD = 3 * 2 * (64 * 256);
    cudaFuncSetAttribute((const void*)mma_fused<true, false, false, false, 32>,
                         cudaFuncAttributeMaxDynamicSharedMemorySize, SM_SF);
    cudaFuncSetAttribute((const void*)mma_fused<false, true, true, true, 64>,
                         cudaFuncAttributeMaxDynamicSharedMemorySize, SM_RF);
    cudaFuncSetAttribute((const void*)mma_down<true, false, false>,
                         cudaFuncAttributeMaxDynamicSharedMemorySize, SM_SD);
    cudaFuncSetAttribute((const void*)mma_down<false, true, true>,
                         cudaFuncAttributeMaxDynamicSharedMemorySize, SM_RD);

    // --- conversions (all streaming, no transpose) ---
    conv_x<<<(T_TOKENS * H_DIM) / 1024, 256>>>(x, xh, xl, xf);
    conv_bf16hl<<<(H_DIM * SI_DIM) / 1024, 256>>>(sg, sgh, sgl);
    conv_bf16hl<<<(H_DIM * SI_DIM) / 1024, 256>>>(su, suh, sul);
    conv_bf16hl<<<(SI_DIM * H_DIM) / 1024, 256>>>(sd, sdh, sdl);
    conv_f16<<<(E_NUM * H_DIM * I_DIM) / 1024, 256>>>(w_gate, wgf);
    conv_f16<<<(E_NUM * H_DIM * I_DIM) / 1024, 256>>>(w_up, wuf);
    conv_f16<<<(E_NUM * I_DIM * H_DIM) / 1024, 256>>>(w_down, wdf);

    // --- routing ---
    zero_kernel<<<1, 32>>>();
    route_kernel<<<T_TOKENS / 256, 256>>>();
    scan_kernel<<<1, 1>>>();
    scatter_kernel<<<T_TOKENS / 256, 256>>>();

    // --- shared expert: fused gate+up (bf16 3-pass) -> hs; down -> out ---
    mma_fused<true, false, false, false, 32>
        <<<dim3(SI_DIM / 128, T_TOKENS / 128, 1), 256, SM_SF>>>(
            xh, xl, sgh, sgl, suh, sul, hsh, hsl, nullptr,
            H_DIM, SI_DIM, T_TOKENS);

    // --- routed experts: fused gate+up (fp16 1-pass, gathered) -> hr ---
    mma_fused<false, true, true, true, 64>
        <<<dim3(I_DIM / 128, SLOTS / 128, E_NUM), 256, SM_RF>>>(
            xf, nullptr, wgf, nullptr, wuf, nullptr, nullptr, nullptr, hrf,
            H_DIM, I_DIM, 0);

    // --- down projections ---
    mma_down<true, false, false>
        <<<dim3(H_DIM / 128, T_TOKENS / 128, 1), 256, SM_SD>>>(
            hsh, hsl, sdh, sdl, out, SI_DIM, H_DIM, T_TOKENS);
    mma_down<false, true, true>
        <<<dim3(H_DIM / 128, SLOTS / 128, E_NUM), 256, SM_RD>>>(
            hrf, nullptr, wdf, nullptr, Yp, I_DIM, H_DIM, 0);

    // --- combine ---
    combine_kernel<<<dim3(H_DIM / 1024, T_TOKENS), 256>>>(out);
}

// round 9
// speedup vs baseline: 4.6973x; 1.4937x over previous
#include <cuda_runtime.h>
#include <cuda_fp16.h>
#include <cstdint>

#define T_TOKENS 4096
#define H_DIM    2048
#define I_DIM    1408
#define E_NUM    16
#define SI_DIM   2816
#define SLOTS    8192   // T * TOP_K

// ---------------- scratch (device globals; no runtime allocation) ----------
__device__ int   g_cnt[E_NUM];
__device__ int   g_off[E_NUM];
__device__ int   g_cur[E_NUM];
__device__ int   g_eid[T_TOKENS * 2];
__device__ float g_wgt[T_TOKENS * 2];
__device__ int   g_slot[T_TOKENS * 2];
__device__ int   g_rowtok[SLOTS];

// fp16 operands (all natural layout; no transposes)
__device__ __half g_xf[T_TOKENS * H_DIM];
__device__ __half g_sgf[H_DIM * SI_DIM];
__device__ __half g_suf[H_DIM * SI_DIM];
__device__ __half g_sdf[SI_DIM * H_DIM];
__device__ __half g_wgf[E_NUM * H_DIM * I_DIM];
__device__ __half g_wuf[E_NUM * H_DIM * I_DIM];
__device__ __half g_wdf[E_NUM * I_DIM * H_DIM];
// intermediate activations
__device__ __half g_hsf[T_TOKENS * SI_DIM];
__device__ __half g_hrf[SLOTS * I_DIM];
__device__ float  g_Y[SLOTS * H_DIM];   // routed down output

// ---------------- threefry2x32 core (verified vs Random123 KAT) -------------
__device__ __forceinline__ uint32_t rotl32(uint32_t v, int r) {
    return (v << r) | (v >> (32 - r));
}

__device__ __forceinline__ void threefry2x32(uint32_t x0, uint32_t x1,
                                             uint32_t& o0, uint32_t& o1) {
    const uint32_t ks0 = 0u, ks1 = 42u, ks2 = 0u ^ 42u ^ 0x1BD11BDAu;
    x0 += ks0; x1 += ks1;
    x0 += x1; x1 = rotl32(x1, 13); x1 ^= x0;
    x0 += x1; x1 = rotl32(x1, 15); x1 ^= x0;
    x0 += x1; x1 = rotl32(x1, 26); x1 ^= x0;
    x0 += x1; x1 = rotl32(x1, 6);  x1 ^= x0;
    x0 += ks1; x1 += ks2 + 1u;
    x0 += x1; x1 = rotl32(x1, 17); x1 ^= x0;
    x0 += x1; x1 = rotl32(x1, 29); x1 ^= x0;
    x0 += x1; x1 = rotl32(x1, 16); x1 ^= x0;
    x0 += x1; x1 = rotl32(x1, 24); x1 ^= x0;
    x0 += ks2; x1 += ks0 + 2u;
    x0 += x1; x1 = rotl32(x1, 13); x1 ^= x0;
    x0 += x1; x1 = rotl32(x1, 15); x1 ^= x0;
    x0 += x1; x1 = rotl32(x1, 26); x1 ^= x0;
    x0 += x1; x1 = rotl32(x1, 6);  x1 ^= x0;
    x0 += ks0; x1 += ks1 + 3u;
    x0 += x1; x1 = rotl32(x1, 17); x1 ^= x0;
    x0 += x1; x1 = rotl32(x1, 29); x1 ^= x0;
    x0 += x1; x1 = rotl32(x1, 16); x1 ^= x0;
    x0 += x1; x1 = rotl32(x1, 24); x1 ^= x0;
    x0 += ks1; x1 += ks2 + 4u;
    x0 += x1; x1 = rotl32(x1, 13); x1 ^= x0;
    x0 += x1; x1 = rotl32(x1, 15); x1 ^= x0;
    x0 += x1; x1 = rotl32(x1, 26); x1 ^= x0;
    x0 += x1; x1 = rotl32(x1, 6);  x1 ^= x0;
    x0 += ks2; x1 += ks0 + 5u;
    o0 = x0; o1 = x1;
}

__device__ __forceinline__ float erfinv_xla(float x) {
    float w = -log1pf(-x * x);
    float p;
    if (w < 5.0f) {
        w -= 2.5f;
        p = 2.81022636e-08f;
        p = fmaf(p, w, 3.43273939e-07f);
        p = fmaf(p, w, -3.5233877e-06f);
        p = fmaf(p, w, -4.39150654e-06f);
        p = fmaf(p, w, 0.00021858087f);
        p = fmaf(p, w, -0.00125372503f);
        p = fmaf(p, w, -0.00417768164f);
        p = fmaf(p, w, 0.246640727f);
        p = fmaf(p, w, 1.50140941f);
    } else {
        w = sqrtf(w) - 3.0f;
        p = -0.000200214257f;
        p = fmaf(p, w, 0.000100950558f);
        p = fmaf(p, w, 0.00134934322f);
        p = fmaf(p, w, -0.00367342844f);
        p = fmaf(p, w, 0.00573950773f);
        p = fmaf(p, w, -0.0076224613f);
        p = fmaf(p, w, 0.00943887047f);
        p = fmaf(p, w, 1.00167406f);
        p = fmaf(p, w, 2.83297682f);
    }
    return p * x;
}

// ---------------- routing kernels ------------------------------------------
__global__ void zero_kernel() {
    if (threadIdx.x < E_NUM) g_cnt[threadIdx.x] = 0;
}

__global__ void route_kernel() {
    int t = blockIdx.x * blockDim.x + threadIdx.x;
    if (t >= T_TOKENS) return;
    float s[E_NUM];
#pragma unroll
    for (int e = 0; e < E_NUM; ++e) {
        uint32_t i = (uint32_t)t * E_NUM + (uint32_t)e;
        uint32_t o0, o1;
        threefry2x32(0u, i, o0, o1);
        uint32_t bits = o0 ^ o1;
        float u01 = __uint_as_float((bits >> 9) | 0x3f800000u) - 1.0f;
        float u = fmaf(u01, 2.0f, -0.99999994f);
        u = fmaxf(-0.99999994f, u);
        float nz = 1.4142135381698608f * erfinv_xla(u);
        s[e] = 1.0f / (1.0f + expf(-nz));
    }
    int b0 = 0;
#pragma unroll
    for (int e = 1; e < E_NUM; ++e) if (s[e] > s[b0]) b0 = e;
    int b1 = (b0 == 0) ? 1 : 0;
#pragma unroll
    for (int e = 0; e < E_NUM; ++e) if (e != b0 && s[e] > s[b1]) b1 = e;
    float sum = s[b0] + s[b1] + 1e-8f;
    g_eid[2 * t + 0] = b0;
    g_eid[2 * t + 1] = b1;
    g_wgt[2 * t + 0] = s[b0] / sum;
    g_wgt[2 * t + 1] = s[b1] / sum;
    atomicAdd(&g_cnt[b0], 1);
    atomicAdd(&g_cnt[b1], 1);
}

__global__ void scan_kernel() {
    int a = 0;
    for (int e = 0; e < E_NUM; ++e) { g_off[e] = a; g_cur[e] = a; a += g_cnt[e]; }
}

__global__ void scatter_kernel() {
    int t = blockIdx.x * blockDim.x + threadIdx.x;
    if (t >= T_TOKENS) return;
#pragma unroll
    for (int k = 0; k < 2; ++k) {
        int e = g_eid[2 * t + k];
        int sidx = atomicAdd(&g_cur[e], 1);
        g_slot[2 * t + k] = sidx;
        g_rowtok[sidx] = t;
    }
}

// ---------------- streaming conversion --------------------------------------
__global__ void conv_f16(const float* __restrict__ src,
                         __half* __restrict__ dst) {
    size_t i = ((size_t)blockIdx.x * blockDim.x + threadIdx.x) * 4;
    float4 v = *(const float4*)(src + i);
    float vv[4] = {v.x, v.y, v.z, v.w};
    __half f[4];
#pragma unroll
    for (int k = 0; k < 4; ++k) f[k] = __float2half_rn(vv[k]);
    *(uint2*)(dst + i) = *(uint2*)f;
}

// ---------------- warp-MMA helpers ------------------------------------------
__device__ __forceinline__ uint32_t smem_u32(const void* p) {
    uint32_t a;
    asm("{ .reg .u64 t; cvta.to.shared.u64 t, %1; cvt.u32.u64 %0, t; }"
        : "=r"(a) : "l"(p));
    return a;
}

__device__ __forceinline__ void cp16(uint32_t s, const void* g) {
    asm volatile("cp.async.cg.shared.global [%0], [%1], 16;"
                 :: "r"(s), "l"(g) : "memory");
}
#define CP_COMMIT() asm volatile("cp.async.commit_group;" ::: "memory")
template <int N>
__device__ __forceinline__ void cp_wait() {
    asm volatile("cp.async.wait_group %0;" :: "n"(N) : "memory");
}

__device__ __forceinline__ void ldsm4(uint32_t* r, uint32_t a) {
    asm volatile("ldmatrix.sync.aligned.m8n8.x4.shared.b16 {%0,%1,%2,%3}, [%4];"
                 : "=r"(r[0]), "=r"(r[1]), "=r"(r[2]), "=r"(r[3]) : "r"(a));
}
__device__ __forceinline__ void ldsm4t(uint32_t* r, uint32_t a) {
    asm volatile("ldmatrix.sync.aligned.m8n8.x4.trans.shared.b16 {%0,%1,%2,%3}, [%4];"
                 : "=r"(r[0]), "=r"(r[1]), "=r"(r[2]), "=r"(r[3]) : "r"(a));
}

__device__ __forceinline__ void mma_f16(float* c, const uint32_t* a,
                                        uint32_t b0, uint32_t b1) {
    asm volatile(
        "mma.sync.aligned.m16n8k16.row.col.f32.f16.f16.f32 "
        "{%0,%1,%2,%3}, {%4,%5,%6,%7}, {%8,%9}, {%0,%1,%2,%3};"
        : "+f"(c[0]), "+f"(c[1]), "+f"(c[2]), "+f"(c[3])
        : "r"(a[0]), "r"(a[1]), "r"(a[2]), "r"(a[3]), "r"(b0), "r"(b1));
}

__device__ __forceinline__ float swiglu_f(float g, float u) {
    return (g / (1.0f + expf(-g))) * u;
}

// A-tile swizzle (128B rows)
__device__ __forceinline__ uint32_t swzA(uint32_t off) {
    return off ^ ((off >> 3) & 0x70u);
}

// =============================================================================
// FUSED gate+up GEMM (fp16 single-pass). A k-major [M][K]; B natural [K][N]
// via ldmatrix.trans. Epilogue -> fp16 swiglu acts.
// CTA 128x128, KC=64, 3 stages (48KB/stage), 8 warps (2x4), warp tile 64x32.
// =============================================================================
template <bool ROUTED, bool GATHER>
__global__ void __launch_bounds__(256, 1)
mma_fused(const __half* __restrict__ Af,
          const __half* __restrict__ B1f, const __half* __restrict__ B2f,
          __half* __restrict__ Ohf, int K, int N, int fixedM)
{
    constexpr int KC   = 64;
    constexpr int TILE = KC * 256;     // 16 KB
    constexpr int STG  = 3 * TILE;     // 48 KB
    constexpr int OF_B1 = TILE;
    constexpr int OF_B2 = 2 * TILE;

    extern __shared__ char smem[];
    const int tid  = threadIdx.x;
    const int wid  = tid >> 5;
    const int lane = tid & 31;

    const int e = blockIdx.z;
    int M, seg;
    if (ROUTED) { M = g_cnt[e]; seg = g_off[e]; }
    else        { M = fixedM;   seg = 0; }
    const int mbase = blockIdx.y * 128;
    if (mbase >= M) return;
    const int nbase = blockIdx.x * 128;

    const uint32_t sb = smem_u32(smem);

    // A loader: row = tid>>1 (0..127), 64B half = (tid&1)*64, 4x16B
    const int lrow = tid >> 1;
    const int hbA  = (tid & 1) * 64;
    uint32_t soA[4];
#pragma unroll
    for (int j = 0; j < 4; ++j)
        soA[j] = swzA((uint32_t)lrow * 128u + (uint32_t)hbA + j * 16u);

    int arow;
    {
        bool v = (mbase + lrow) < M;
        if (ROUTED) {
            int slot = seg + mbase + lrow;
            if (GATHER) arow = v ? g_rowtok[slot] : 0;
            else        arow = v ? slot : seg;
        } else arow = mbase + lrow;
    }
    const char* gA = (const char*)(Af + (size_t)arow * K) + hbA;

    // B loader: tile rows = k (64 rows x 256B), 4 threads/row
    const int bk  = tid >> 2;
    const int bnb = (tid & 3) * 64;
    uint32_t soB[4];
#pragma unroll
    for (int j = 0; j < 4; ++j)
        soB[j] = (uint32_t)bk * 256u + (((uint32_t)bnb + j * 16u) ^ (((uint32_t)bk & 7u) << 4));

    const size_t bexp = ROUTED ? (size_t)e * (size_t)K * (size_t)N : 0;
    const size_t brow = bexp + (size_t)bk * N + nbase;
    const char* gB1 = (const char*)(B1f + brow) + bnb;
    const char* gB2 = (const char*)(B2f + brow) + bnb;
    const size_t bstep = (size_t)KC * N * 2;

    const int nk = K / KC;

#define ISSUE_F(slot, kt)                                                       \
    do {                                                                        \
        uint32_t b_ = sb + (uint32_t)(slot) * STG;                              \
        size_t ak_ = (size_t)(kt) * 128;                                        \
        size_t bk_ = (size_t)(kt) * bstep;                                      \
        _Pragma("unroll")                                                       \
        for (int j_ = 0; j_ < 4; ++j_) {                                        \
            cp16(b_ + soA[j_],         gA  + ak_ + j_ * 16);                    \
            cp16(b_ + OF_B1 + soB[j_], gB1 + bk_ + j_ * 16);                    \
            cp16(b_ + OF_B2 + soB[j_], gB2 + bk_ + j_ * 16);                    \
        }                                                                       \
        CP_COMMIT();                                                            \
    } while (0)

    const int wm = (wid >> 2) * 64;
    const int wn = (wid & 3) * 32;

    uint32_t aOff[4];
#pragma unroll
    for (int mf = 0; mf < 4; ++mf)
        aOff[mf] = (uint32_t)(wm + mf * 16 + (lane & 15)) * 128u
                 + (uint32_t)((lane >> 4) * 16);
    uint32_t bB[2];
    {
        uint32_t r = lane & 7u, m = lane >> 3;
#pragma unroll
        for (int nf2 = 0; nf2 < 2; ++nf2) {
            uint32_t nb = (uint32_t)(wn + nf2 * 16 + (int)((m >> 1) * 8)) * 2u;
            bB[nf2] = ((m & 1u) * 8u + r) * 256u + (nb ^ (r << 4));
        }
    }

    float accG[4][4][4], accU[4][4][4];
#pragma unroll
    for (int i = 0; i < 4; ++i)
#pragma unroll
        for (int j = 0; j < 4; ++j)
#pragma unroll
            for (int q = 0; q < 4; ++q) { accG[i][j][q] = 0.f; accU[i][j][q] = 0.f; }

    ISSUE_F(0, 0);
    ISSUE_F(1, 1);

    for (int kt = 0; kt < nk; ++kt) {
        const int s = kt % 3;
        if (kt + 1 < nk) cp_wait<1>(); else cp_wait<0>();
        __syncthreads();
        if (kt + 2 < nk) ISSUE_F((kt + 2) % 3, kt + 2);

        const uint32_t stb = sb + (uint32_t)s * STG;
#pragma unroll
        for (int ks = 0; ks < 4; ++ks) {
            uint32_t a[4][4], b1[2][4], b2[2][4];
#pragma unroll
            for (int mf = 0; mf < 4; ++mf)
                ldsm4(a[mf], stb + swzA(aOff[mf] + ks * 32u));
#pragma unroll
            for (int nf2 = 0; nf2 < 2; ++nf2) {
                uint32_t off = bB[nf2] + ks * 4096u;
                ldsm4t(b1[nf2], stb + OF_B1 + off);
                ldsm4t(b2[nf2], stb + OF_B2 + off);
            }
#pragma unroll
            for (int mf = 0; mf < 4; ++mf)
#pragma unroll
                for (int nf = 0; nf < 4; ++nf)
                    mma_f16(accG[mf][nf], a[mf],
                            b1[nf >> 1][(nf & 1) * 2], b1[nf >> 1][(nf & 1) * 2 + 1]);
#pragma unroll
            for (int mf = 0; mf < 4; ++mf)
#pragma unroll
                for (int nf = 0; nf < 4; ++nf)
                    mma_f16(accU[mf][nf], a[mf],
                            b2[nf >> 1][(nf & 1) * 2], b2[nf >> 1][(nf & 1) * 2 + 1]);
        }
    }
#undef ISSUE_F

    const size_t rowoff = ROUTED ? (size_t)seg : 0;
#pragma unroll
    for (int mf = 0; mf < 4; ++mf) {
#pragma unroll
        for (int nf = 0; nf < 4; ++nf) {
            int r0 = mbase + wm + mf * 16 + (lane >> 2);
            int n0 = nbase + wn + nf * 8 + (lane & 3) * 2;
            float* cg = accG[mf][nf];
            float* cu = accU[mf][nf];
#pragma unroll
            for (int h = 0; h < 2; ++h) {
                int r = r0 + h * 8;
                if (r < M) {
                    size_t idx = (rowoff + r) * (size_t)N + n0;
                    float a0 = swiglu_f(cg[h * 2 + 0], cu[h * 2 + 0]);
                    float a1 = swiglu_f(cg[h * 2 + 1], cu[h * 2 + 1]);
                    __half2 hp = __floats2half2_rn(a0, a1);
                    *(uint32_t*)&Ohf[idx] = *reinterpret_cast<uint32_t*>(&hp);
                }
            }
        }
    }
}

// =============================================================================
// DOWN GEMM (fp16 single-pass). A k-major; B natural [K][N]; out fp32.
// CTA 128x128, KC=64, 3 stages (32KB/stage).
// =============================================================================
template <bool ROUTED>
__global__ void __launch_bounds__(256, 1)
mma_down(const __half* __restrict__ Af, const __half* __restrict__ Bf,
         float* __restrict__ Cf, int K, int N, int fixedM)
{
    constexpr int KC   = 64;
    constexpr int TILE = KC * 256;
    constexpr int STG  = 2 * TILE;     // 32 KB
    constexpr int OF_B = TILE;

    extern __shared__ char smem[];
    const int tid  = threadIdx.x;
    const int wid  = tid >> 5;
    const int lane = tid & 31;

    const int e = blockIdx.z;
    int M, seg;
    if (ROUTED) { M = g_cnt[e]; seg = g_off[e]; }
    else        { M = fixedM;   seg = 0; }
    const int mbase = blockIdx.y * 128;
    if (mbase >= M) return;
    const int nbase = blockIdx.x * 128;

    const uint32_t sb = smem_u32(smem);

    const int lrow = tid >> 1;
    const int hbA  = (tid & 1) * 64;
    uint32_t soA[4];
#pragma unroll
    for (int j = 0; j < 4; ++j)
        soA[j] = swzA((uint32_t)lrow * 128u + (uint32_t)hbA + j * 16u);

    int arow;
    {
        bool v = (mbase + lrow) < M;
        if (ROUTED) arow = v ? (seg + mbase + lrow) : seg;
        else        arow = mbase + lrow;
    }
    const char* gA = (const char*)(Af + (size_t)arow * K) + hbA;

    const int bk  = tid >> 2;
    const int bnb = (tid & 3) * 64;
    uint32_t soB[4];
#pragma unroll
    for (int j = 0; j < 4; ++j)
        soB[j] = (uint32_t)bk * 256u + (((uint32_t)bnb + j * 16u) ^ (((uint32_t)bk & 7u) << 4));

    const size_t bexp = ROUTED ? (size_t)e * (size_t)K * (size_t)N : 0;
    const size_t brow = bexp + (size_t)bk * N + nbase;
    const char* gB = (const char*)(Bf + brow) + bnb;
    const size_t bstep = (size_t)KC * N * 2;

    const int nk = K / KC;

#define ISSUE_D(slot, kt)                                                       \
    do {                                                                        \
        uint32_t b_ = sb + (uint32_t)(slot) * STG;                              \
        size_t ak_ = (size_t)(kt) * 128;                                        \
        size_t bk_ = (size_t)(kt) * bstep;                                      \
        _Pragma("unroll")                                                       \
        for (int j_ = 0; j_ < 4; ++j_) {                                        \
            cp16(b_ + soA[j_],        gA + ak_ + j_ * 16);                      \
            cp16(b_ + OF_B + soB[j_], gB + bk_ + j_ * 16);                      \
        }                                                                       \
        CP_COMMIT();                                                            \
    } while (0)

    const int wm = (wid >> 2) * 64;
    const int wn = (wid & 3) * 32;

    uint32_t aOff[4];
#pragma unroll
    for (int mf = 0; mf < 4; ++mf)
        aOff[mf] = (uint32_t)(wm + mf * 16 + (lane & 15)) * 128u
                 + (uint32_t)((lane >> 4) * 16);
    uint32_t bB[2];
    {
        uint32_t r = lane & 7u, m = lane >> 3;
#pragma unroll
        for (int nf2 = 0; nf2 < 2; ++nf2) {
            uint32_t nb = (uint32_t)(wn + nf2 * 16 + (int)((m >> 1) * 8)) * 2u;
            bB[nf2] = ((m & 1u) * 8u + r) * 256u + (nb ^ (r << 4));
        }
    }

    float acc[4][4][4];
#pragma unroll
    for (int i = 0; i < 4; ++i)
#pragma unroll
        for (int j = 0; j < 4; ++j)
#pragma unroll
            for (int q = 0; q < 4; ++q) acc[i][j][q] = 0.f;

    ISSUE_D(0, 0);
    ISSUE_D(1, 1);

    for (int kt = 0; kt < nk; ++kt) {
        const int s = kt % 3;
        if (kt + 1 < nk) cp_wait<1>(); else cp_wait<0>();
        __syncthreads();
        if (kt + 2 < nk) ISSUE_D((kt + 2) % 3, kt + 2);

        const uint32_t stb = sb + (uint32_t)s * STG;
#pragma unroll
        for (int ks = 0; ks < 4; ++ks) {
            uint32_t a[4][4], b[2][4];
#pragma unroll
            for (int mf = 0; mf < 4; ++mf)
                ldsm4(a[mf], stb + swzA(aOff[mf] + ks * 32u));
#pragma unroll
            for (int nf2 = 0; nf2 < 2; ++nf2)
                ldsm4t(b[nf2], stb + OF_B + bB[nf2] + ks * 4096u);
#pragma unroll
            for (int mf = 0; mf < 4; ++mf)
#pragma unroll
                for (int nf = 0; nf < 4; ++nf)
                    mma_f16(acc[mf][nf], a[mf],
                            b[nf >> 1][(nf & 1) * 2], b[nf >> 1][(nf & 1) * 2 + 1]);
        }
    }
#undef ISSUE_D

    const size_t rowoff = ROUTED ? (size_t)seg : 0;
#pragma unroll
    for (int mf = 0; mf < 4; ++mf) {
#pragma unroll
        for (int nf = 0; nf < 4; ++nf) {
            int r0 = mbase + wm + mf * 16 + (lane >> 2);
            int n0 = nbase + wn + nf * 8 + (lane & 3) * 2;
            float* c = acc[mf][nf];
            if (r0 < M)
                *(float2*)&Cf[(rowoff + r0) * (size_t)N + n0] = make_float2(c[0], c[1]);
            if (r0 + 8 < M)
                *(float2*)&Cf[(rowoff + r0 + 8) * (size_t)N + n0] = make_float2(c[2], c[3]);
        }
    }
}

// ---------------- combine: out += w0*Y[slot0] + w1*Y[slot1] ------------------
__global__ void combine_kernel(float* __restrict__ out) {
    int t = blockIdx.y;
    int c = (blockIdx.x * blockDim.x + threadIdx.x) * 4;
    int s0 = g_slot[2 * t + 0], s1 = g_slot[2 * t + 1];
    float w0 = g_wgt[2 * t + 0], w1 = g_wgt[2 * t + 1];
    const float4 y0 = *(const float4*)&g_Y[(size_t)s0 * H_DIM + c];
    const float4 y1 = *(const float4*)&g_Y[(size_t)s1 * H_DIM + c];
    float4 o = *(float4*)&out[(size_t)t * H_DIM + c];
    o.x += w0 * y0.x + w1 * y1.x;
    o.y += w0 * y0.y + w1 * y1.y;
    o.z += w0 * y0.z + w1 * y1.z;
    o.w += w0 * y0.w + w1 * y1.w;
    *(float4*)&out[(size_t)t * H_DIM + c] = o;
}

// ---------------- launch -----------------------------------------------------
extern "C" void kernel_launch(void* const* d_in, const int* in_sizes, int n_in,
                              void* d_out, int out_size) {
    (void)in_sizes; (void)n_in; (void)out_size;
    const float* x      = (const float*)d_in[0];
    // d_in[1] router_w, d_in[2] router_b: dead inputs (RandomSTE forward = noise)
    const float* w_gate = (const float*)d_in[3];
    const float* w_up   = (const float*)d_in[4];
    const float* w_down = (const float*)d_in[5];
    const float* sg     = (const float*)d_in[6];
    const float* su     = (const float*)d_in[7];
    const float* sd     = (const float*)d_in[8];
    float* out = (float*)d_out;

    auto sym = [](const void* s) {
        void* p = nullptr;
        cudaGetSymbolAddress(&p, s);
        return p;
    };
    __half* xf  = (__half*)sym(g_xf);
    __half* sgf = (__half*)sym(g_sgf);
    __half* suf = (__half*)sym(g_suf);
    __half* sdf = (__half*)sym(g_sdf);
    __half* wgf = (__half*)sym(g_wgf);
    __half* wuf = (__half*)sym(g_wuf);
    __half* wdf = (__half*)sym(g_wdf);
    __half* hsf = (__half*)sym(g_hsf);
    __half* hrf = (__half*)sym(g_hrf);
    float*  Yp  = (float*)sym(g_Y);

    const int SM_F = 3 * 3 * (64 * 256);   // 147456
    const int SM_D = 3 * 2 * (64 * 256);   // 98304
    cudaFuncSetAttribute((const void*)mma_fused<false, false>,
                         cudaFuncAttributeMaxDynamicSharedMemorySize, SM_F);
    cudaFuncSetAttribute((const void*)mma_fused<true, true>,
                         cudaFuncAttributeMaxDynamicSharedMemorySize, SM_F);
    cudaFuncSetAttribute((const void*)mma_down<false>,
                         cudaFuncAttributeMaxDynamicSharedMemorySize, SM_D);
    cudaFuncSetAttribute((const void*)mma_down<true>,
                         cudaFuncAttributeMaxDynamicSharedMemorySize, SM_D);

    // --- conversions (pure streaming fp32 -> fp16) ---
    conv_f16<<<(T_TOKENS * H_DIM) / 1024, 256>>>(x, xf);
    conv_f16<<<(H_DIM * SI_DIM) / 1024, 256>>>(sg, sgf);
    conv_f16<<<(H_DIM * SI_DIM) / 1024, 256>>>(su, suf);
    conv_f16<<<(SI_DIM * H_DIM) / 1024, 256>>>(sd, sdf);
    conv_f16<<<(E_NUM * H_DIM * I_DIM) / 1024, 256>>>(w_gate, wgf);
    conv_f16<<<(E_NUM * H_DIM * I_DIM) / 1024, 256>>>(w_up, wuf);
    conv_f16<<<(E_NUM * I_DIM * H_DIM) / 1024, 256>>>(w_down, wdf);

    // --- routing ---
    zero_kernel<<<1, 32>>>();
    route_kernel<<<T_TOKENS / 256, 256>>>();
    scan_kernel<<<1, 1>>>();
    scatter_kernel<<<T_TOKENS / 256, 256>>>();

    // --- shared expert: fused gate+up -> hs; routed: fused (gathered) -> hr ---
    mma_fused<false, false>
        <<<dim3(SI_DIM / 128, T_TOKENS / 128, 1), 256, SM_F>>>(
            xf, sgf, suf, hsf, H_DIM, SI_DIM, T_TOKENS);
    mma_fused<true, true>
        <<<dim3(I_DIM / 128, SLOTS / 128, E_NUM), 256, SM_F>>>(
            xf, wgf, wuf, hrf, H_DIM, I_DIM, 0);

    // --- down projections: shared -> out (overwrite), routed -> Y ---
    mma_down<false>
        <<<dim3(H_DIM / 128, T_TOKENS / 128, 1), 256, SM_D>>>(
            hsf, sdf, out, SI_DIM, H_DIM, T_TOKENS);
    mma_down<true>
        <<<dim3(H_DIM / 128, SLOTS / 128, E_NUM), 256, SM_D>>>(
            hrf, wdf, Yp, I_DIM, H_DIM, 0);

    // --- combine ---
    combine_kernel<<<dim3(H_DIM / 1024, T_TOKENS), 256>>>(out);
}

// round 10
// speedup vs baseline: 5.6783x; 1.2089x over previous
#include <cuda_runtime.h>
#include <cuda_fp16.h>
#include <cstdint>

#define T_TOKENS 4096
#define H_DIM    2048
#define I_DIM    1408
#define E_NUM    16
#define SI_DIM   2816
#define SLOTS    8192   // T * TOP_K

// ---------------- scratch (device globals; no runtime allocation) ----------
__device__ int   g_cnt[E_NUM];
__device__ int   g_off[E_NUM];
__device__ int   g_cur[E_NUM];
__device__ int   g_eid[T_TOKENS * 2];
__device__ float g_wgt[T_TOKENS * 2];
__device__ int   g_slot[T_TOKENS * 2];
__device__ int   g_rowtok[SLOTS];

// fp16 operands (all natural layout; no transposes)
__device__ __half g_xf[T_TOKENS * H_DIM];
__device__ __half g_sgf[H_DIM * SI_DIM];
__device__ __half g_suf[H_DIM * SI_DIM];
__device__ __half g_sdf[SI_DIM * H_DIM];
__device__ __half g_wgf[E_NUM * H_DIM * I_DIM];
__device__ __half g_wuf[E_NUM * H_DIM * I_DIM];
__device__ __half g_wdf[E_NUM * I_DIM * H_DIM];
// intermediate activations
__device__ __half g_hsf[T_TOKENS * SI_DIM];
__device__ __half g_hrf[SLOTS * I_DIM];
__device__ float  g_Y[SLOTS * H_DIM];   // routed down output

// ---------------- threefry2x32 core (verified vs Random123 KAT) -------------
__device__ __forceinline__ uint32_t rotl32(uint32_t v, int r) {
    return (v << r) | (v >> (32 - r));
}

__device__ __forceinline__ void threefry2x32(uint32_t x0, uint32_t x1,
                                             uint32_t& o0, uint32_t& o1) {
    const uint32_t ks0 = 0u, ks1 = 42u, ks2 = 0u ^ 42u ^ 0x1BD11BDAu;
    x0 += ks0; x1 += ks1;
    x0 += x1; x1 = rotl32(x1, 13); x1 ^= x0;
    x0 += x1; x1 = rotl32(x1, 15); x1 ^= x0;
    x0 += x1; x1 = rotl32(x1, 26); x1 ^= x0;
    x0 += x1; x1 = rotl32(x1, 6);  x1 ^= x0;
    x0 += ks1; x1 += ks2 + 1u;
    x0 += x1; x1 = rotl32(x1, 17); x1 ^= x0;
    x0 += x1; x1 = rotl32(x1, 29); x1 ^= x0;
    x0 += x1; x1 = rotl32(x1, 16); x1 ^= x0;
    x0 += x1; x1 = rotl32(x1, 24); x1 ^= x0;
    x0 += ks2; x1 += ks0 + 2u;
    x0 += x1; x1 = rotl32(x1, 13); x1 ^= x0;
    x0 += x1; x1 = rotl32(x1, 15); x1 ^= x0;
    x0 += x1; x1 = rotl32(x1, 26); x1 ^= x0;
    x0 += x1; x1 = rotl32(x1, 6);  x1 ^= x0;
    x0 += ks0; x1 += ks1 + 3u;
    x0 += x1; x1 = rotl32(x1, 17); x1 ^= x0;
    x0 += x1; x1 = rotl32(x1, 29); x1 ^= x0;
    x0 += x1; x1 = rotl32(x1, 16); x1 ^= x0;
    x0 += x1; x1 = rotl32(x1, 24); x1 ^= x0;
    x0 += ks1; x1 += ks2 + 4u;
    x0 += x1; x1 = rotl32(x1, 13); x1 ^= x0;
    x0 += x1; x1 = rotl32(x1, 15); x1 ^= x0;
    x0 += x1; x1 = rotl32(x1, 26); x1 ^= x0;
    x0 += x1; x1 = rotl32(x1, 6);  x1 ^= x0;
    x0 += ks2; x1 += ks0 + 5u;
    o0 = x0; o1 = x1;
}

__device__ __forceinline__ float erfinv_xla(float x) {
    float w = -log1pf(-x * x);
    float p;
    if (w < 5.0f) {
        w -= 2.5f;
        p = 2.81022636e-08f;
        p = fmaf(p, w, 3.43273939e-07f);
        p = fmaf(p, w, -3.5233877e-06f);
        p = fmaf(p, w, -4.39150654e-06f);
        p = fmaf(p, w, 0.00021858087f);
        p = fmaf(p, w, -0.00125372503f);
        p = fmaf(p, w, -0.00417768164f);
        p = fmaf(p, w, 0.246640727f);
        p = fmaf(p, w, 1.50140941f);
    } else {
        w = sqrtf(w) - 3.0f;
        p = -0.000200214257f;
        p = fmaf(p, w, 0.000100950558f);
        p = fmaf(p, w, 0.00134934322f);
        p = fmaf(p, w, -0.00367342844f);
        p = fmaf(p, w, 0.00573950773f);
        p = fmaf(p, w, -0.0076224613f);
        p = fmaf(p, w, 0.00943887047f);
        p = fmaf(p, w, 1.00167406f);
        p = fmaf(p, w, 2.83297682f);
    }
    return p * x;
}

// ---------------- routing kernels ------------------------------------------
__global__ void zero_kernel() {
    if (threadIdx.x < E_NUM) g_cnt[threadIdx.x] = 0;
}

__global__ void route_kernel() {
    int t = blockIdx.x * blockDim.x + threadIdx.x;
    if (t >= T_TOKENS) return;
    float s[E_NUM];
#pragma unroll
    for (int e = 0; e < E_NUM; ++e) {
        uint32_t i = (uint32_t)t * E_NUM + (uint32_t)e;
        uint32_t o0, o1;
        threefry2x32(0u, i, o0, o1);
        uint32_t bits = o0 ^ o1;
        float u01 = __uint_as_float((bits >> 9) | 0x3f800000u) - 1.0f;
        float u = fmaf(u01, 2.0f, -0.99999994f);
        u = fmaxf(-0.99999994f, u);
        float nz = 1.4142135381698608f * erfinv_xla(u);
        s[e] = 1.0f / (1.0f + expf(-nz));
    }
    int b0 = 0;
#pragma unroll
    for (int e = 1; e < E_NUM; ++e) if (s[e] > s[b0]) b0 = e;
    int b1 = (b0 == 0) ? 1 : 0;
#pragma unroll
    for (int e = 0; e < E_NUM; ++e) if (e != b0 && s[e] > s[b1]) b1 = e;
    float sum = s[b0] + s[b1] + 1e-8f;
    g_eid[2 * t + 0] = b0;
    g_eid[2 * t + 1] = b1;
    g_wgt[2 * t + 0] = s[b0] / sum;
    g_wgt[2 * t + 1] = s[b1] / sum;
    atomicAdd(&g_cnt[b0], 1);
    atomicAdd(&g_cnt[b1], 1);
}

__global__ void scan_kernel() {
    int a = 0;
    for (int e = 0; e < E_NUM; ++e) { g_off[e] = a; g_cur[e] = a; a += g_cnt[e]; }
}

__global__ void scatter_kernel() {
    int t = blockIdx.x * blockDim.x + threadIdx.x;
    if (t >= T_TOKENS) return;
#pragma unroll
    for (int k = 0; k < 2; ++k) {
        int e = g_eid[2 * t + k];
        int sidx = atomicAdd(&g_cur[e], 1);
        g_slot[2 * t + k] = sidx;
        g_rowtok[sidx] = t;
    }
}

// ---------------- streaming conversion (MLP=4: 4 independent float4 loads) --
__global__ void conv_f16(const float* __restrict__ src,
                         __half* __restrict__ dst) {
    size_t t = (size_t)blockIdx.x * blockDim.x + threadIdx.x;
    size_t stride = (size_t)gridDim.x * blockDim.x;
    float4 v[4];
#pragma unroll
    for (int j = 0; j < 4; ++j)
        v[j] = *(const float4*)(src + 4 * (t + j * stride));
#pragma unroll
    for (int j = 0; j < 4; ++j) {
        __half f[4];
        f[0] = __float2half_rn(v[j].x);
        f[1] = __float2half_rn(v[j].y);
        f[2] = __float2half_rn(v[j].z);
        f[3] = __float2half_rn(v[j].w);
        *(uint2*)(dst + 4 * (t + j * stride)) = *(uint2*)f;
    }
}

// ---------------- warp-MMA helpers ------------------------------------------
__device__ __forceinline__ uint32_t smem_u32(const void* p) {
    uint32_t a;
    asm("{ .reg .u64 t; cvta.to.shared.u64 t, %1; cvt.u32.u64 %0, t; }"
        : "=r"(a) : "l"(p));
    return a;
}

__device__ __forceinline__ void cp16(uint32_t s, const void* g) {
    asm volatile("cp.async.cg.shared.global [%0], [%1], 16;"
                 :: "r"(s), "l"(g) : "memory");
}
#define CP_COMMIT() asm volatile("cp.async.commit_group;" ::: "memory")
template <int N>
__device__ __forceinline__ void cp_wait() {
    asm volatile("cp.async.wait_group %0;" :: "n"(N) : "memory");
}

__device__ __forceinline__ void ldsm4(uint32_t* r, uint32_t a) {
    asm volatile("ldmatrix.sync.aligned.m8n8.x4.shared.b16 {%0,%1,%2,%3}, [%4];"
                 : "=r"(r[0]), "=r"(r[1]), "=r"(r[2]), "=r"(r[3]) : "r"(a));
}
__device__ __forceinline__ void ldsm4t(uint32_t* r, uint32_t a) {
    asm volatile("ldmatrix.sync.aligned.m8n8.x4.trans.shared.b16 {%0,%1,%2,%3}, [%4];"
                 : "=r"(r[0]), "=r"(r[1]), "=r"(r[2]), "=r"(r[3]) : "r"(a));
}

__device__ __forceinline__ void mma_f16(float* c, const uint32_t* a,
                                        uint32_t b0, uint32_t b1) {
    asm volatile(
        "mma.sync.aligned.m16n8k16.row.col.f32.f16.f16.f32 "
        "{%0,%1,%2,%3}, {%4,%5,%6,%7}, {%8,%9}, {%0,%1,%2,%3};"
        : "+f"(c[0]), "+f"(c[1]), "+f"(c[2]), "+f"(c[3])
        : "r"(a[0]), "r"(a[1]), "r"(a[2]), "r"(a[3]), "r"(b0), "r"(b1));
}

__device__ __forceinline__ float swiglu_f(float g, float u) {
    return (g / (1.0f + expf(-g))) * u;
}

// A-tile swizzle (128B rows)
__device__ __forceinline__ uint32_t swzA(uint32_t off) {
    return off ^ ((off >> 3) & 0x70u);
}

// =============================================================================
// FUSED gate+up GEMM (fp16 single-pass). A k-major [M][K]; B natural [K][N]
// via ldmatrix.trans. Epilogue -> fp16 swiglu acts.
// CTA 128x128, KC=64, 3 stages (48KB/stage), 8 warps (2x4), warp tile 64x32.
// =============================================================================
template <bool ROUTED, bool GATHER>
__global__ void __launch_bounds__(256, 1)
mma_fused(const __half* __restrict__ Af,
          const __half* __restrict__ B1f, const __half* __restrict__ B2f,
          __half* __restrict__ Ohf, int K, int N, int fixedM)
{
    constexpr int KC   = 64;
    constexpr int TILE = KC * 256;     // 16 KB
    constexpr int STG  = 3 * TILE;     // 48 KB
    constexpr int OF_B1 = TILE;
    constexpr int OF_B2 = 2 * TILE;

    extern __shared__ char smem[];
    const int tid  = threadIdx.x;
    const int wid  = tid >> 5;
    const int lane = tid & 31;

    const int e = blockIdx.z;
    int M, seg;
    if (ROUTED) { M = g_cnt[e]; seg = g_off[e]; }
    else        { M = fixedM;   seg = 0; }
    const int mbase = blockIdx.y * 128;
    if (mbase >= M) return;
    const int nbase = blockIdx.x * 128;

    const uint32_t sb = smem_u32(smem);

    // A loader: row = tid>>1 (0..127), 64B half = (tid&1)*64, 4x16B
    const int lrow = tid >> 1;
    const int hbA  = (tid & 1) * 64;
    uint32_t soA[4];
#pragma unroll
    for (int j = 0; j < 4; ++j)
        soA[j] = swzA((uint32_t)lrow * 128u + (uint32_t)hbA + j * 16u);

    int arow;
    {
        bool v = (mbase + lrow) < M;
        if (ROUTED) {
            int slot = seg + mbase + lrow;
            if (GATHER) arow = v ? g_rowtok[slot] : 0;
            else        arow = v ? slot : seg;
        } else arow = mbase + lrow;
    }
    const char* gA = (const char*)(Af + (size_t)arow * K) + hbA;

    // B loader: tile rows = k (64 rows x 256B), 4 threads/row
    const int bk  = tid >> 2;
    const int bnb = (tid & 3) * 64;
    uint32_t soB[4];
#pragma unroll
    for (int j = 0; j < 4; ++j)
        soB[j] = (uint32_t)bk * 256u + (((uint32_t)bnb + j * 16u) ^ (((uint32_t)bk & 7u) << 4));

    const size_t bexp = ROUTED ? (size_t)e * (size_t)K * (size_t)N : 0;
    const size_t brow = bexp + (size_t)bk * N + nbase;
    const char* gB1 = (const char*)(B1f + brow) + bnb;
    const char* gB2 = (const char*)(B2f + brow) + bnb;
    const size_t bstep = (size_t)KC * N * 2;

    const int nk = K / KC;

#define ISSUE_F(slot, kt)                                                       \
    do {                                                                        \
        uint32_t b_ = sb + (uint32_t)(slot) * STG;                              \
        size_t ak_ = (size_t)(kt) * 128;                                        \
        size_t bk_ = (size_t)(kt) * bstep;                                      \
        _Pragma("unroll")                                                       \
        for (int j_ = 0; j_ < 4; ++j_) {                                        \
            cp16(b_ + soA[j_],         gA  + ak_ + j_ * 16);                    \
            cp16(b_ + OF_B1 + soB[j_], gB1 + bk_ + j_ * 16);                    \
            cp16(b_ + OF_B2 + soB[j_], gB2 + bk_ + j_ * 16);                    \
        }                                                                       \
        CP_COMMIT();                                                            \
    } while (0)

    const int wm = (wid >> 2) * 64;
    const int wn = (wid & 3) * 32;

    uint32_t aOff[4];
#pragma unroll
    for (int mf = 0; mf < 4; ++mf)
        aOff[mf] = (uint32_t)(wm + mf * 16 + (lane & 15)) * 128u
                 + (uint32_t)((lane >> 4) * 16);
    uint32_t bB[2];
    {
        uint32_t r = lane & 7u, m = lane >> 3;
#pragma unroll
        for (int nf2 = 0; nf2 < 2; ++nf2) {
            uint32_t nb = (uint32_t)(wn + nf2 * 16 + (int)((m >> 1) * 8)) * 2u;
            bB[nf2] = ((m & 1u) * 8u + r) * 256u + (nb ^ (r << 4));
        }
    }

    float accG[4][4][4], accU[4][4][4];
#pragma unroll
    for (int i = 0; i < 4; ++i)
#pragma unroll
        for (int j = 0; j < 4; ++j)
#pragma unroll
            for (int q = 0; q < 4; ++q) { accG[i][j][q] = 0.f; accU[i][j][q] = 0.f; }

    ISSUE_F(0, 0);
    ISSUE_F(1, 1);

    for (int kt = 0; kt < nk; ++kt) {
        const int s = kt % 3;
        if (kt + 1 < nk) cp_wait<1>(); else cp_wait<0>();
        __syncthreads();
        if (kt + 2 < nk) ISSUE_F((kt + 2) % 3, kt + 2);

        const uint32_t stb = sb + (uint32_t)s * STG;
#pragma unroll
        for (int ks = 0; ks < 4; ++ks) {
            uint32_t a[4][4], b1[2][4], b2[2][4];
#pragma unroll
            for (int mf = 0; mf < 4; ++mf)
                ldsm4(a[mf], stb + swzA(aOff[mf] + ks * 32u));
#pragma unroll
            for (int nf2 = 0; nf2 < 2; ++nf2) {
                uint32_t off = bB[nf2] + ks * 4096u;
                ldsm4t(b1[nf2], stb + OF_B1 + off);
                ldsm4t(b2[nf2], stb + OF_B2 + off);
            }
#pragma unroll
            for (int mf = 0; mf < 4; ++mf)
#pragma unroll
                for (int nf = 0; nf < 4; ++nf)
                    mma_f16(accG[mf][nf], a[mf],
                            b1[nf >> 1][(nf & 1) * 2], b1[nf >> 1][(nf & 1) * 2 + 1]);
#pragma unroll
            for (int mf = 0; mf < 4; ++mf)
#pragma unroll
                for (int nf = 0; nf < 4; ++nf)
                    mma_f16(accU[mf][nf], a[mf],
                            b2[nf >> 1][(nf & 1) * 2], b2[nf >> 1][(nf & 1) * 2 + 1]);
        }
    }
#undef ISSUE_F

    const size_t rowoff = ROUTED ? (size_t)seg : 0;
#pragma unroll
    for (int mf = 0; mf < 4; ++mf) {
#pragma unroll
        for (int nf = 0; nf < 4; ++nf) {
            int r0 = mbase + wm + mf * 16 + (lane >> 2);
            int n0 = nbase + wn + nf * 8 + (lane & 3) * 2;
            float* cg = accG[mf][nf];
            float* cu = accU[mf][nf];
#pragma unroll
            for (int h = 0; h < 2; ++h) {
                int r = r0 + h * 8;
                if (r < M) {
                    size_t idx = (rowoff + r) * (size_t)N + n0;
                    float a0 = swiglu_f(cg[h * 2 + 0], cu[h * 2 + 0]);
                    float a1 = swiglu_f(cg[h * 2 + 1], cu[h * 2 + 1]);
                    __half2 hp = __floats2half2_rn(a0, a1);
                    *(uint32_t*)&Ohf[idx] = *reinterpret_cast<uint32_t*>(&hp);
                }
            }
        }
    }
}

// =============================================================================
// DOWN GEMM (fp16 single-pass). A k-major; B natural [K][N]; out fp32.
// CTA 128x128, KC=64, 3 stages (32KB/stage).
// =============================================================================
template <bool ROUTED>
__global__ void __launch_bounds__(256, 1)
mma_down(const __half* __restrict__ Af, const __half* __restrict__ Bf,
         float* __restrict__ Cf, int K, int N, int fixedM)
{
    constexpr int KC   = 64;
    constexpr int TILE = KC * 256;
    constexpr int STG  = 2 * TILE;     // 32 KB
    constexpr int OF_B = TILE;

    extern __shared__ char smem[];
    const int tid  = threadIdx.x;
    const int wid  = tid >> 5;
    const int lane = tid & 31;

    const int e = blockIdx.z;
    int M, seg;
    if (ROUTED) { M = g_cnt[e]; seg = g_off[e]; }
    else        { M = fixedM;   seg = 0; }
    const int mbase = blockIdx.y * 128;
    if (mbase >= M) return;
    const int nbase = blockIdx.x * 128;

    const uint32_t sb = smem_u32(smem);

    const int lrow = tid >> 1;
    const int hbA  = (tid & 1) * 64;
    uint32_t soA[4];
#pragma unroll
    for (int j = 0; j < 4; ++j)
        soA[j] = swzA((uint32_t)lrow * 128u + (uint32_t)hbA + j * 16u);

    int arow;
    {
        bool v = (mbase + lrow) < M;
        if (ROUTED) arow = v ? (seg + mbase + lrow) : seg;
        else        arow = mbase + lrow;
    }
    const char* gA = (const char*)(Af + (size_t)arow * K) + hbA;

    const int bk  = tid >> 2;
    const int bnb = (tid & 3) * 64;
    uint32_t soB[4];
#pragma unroll
    for (int j = 0; j < 4; ++j)
        soB[j] = (uint32_t)bk * 256u + (((uint32_t)bnb + j * 16u) ^ (((uint32_t)bk & 7u) << 4));

    const size_t bexp = ROUTED ? (size_t)e * (size_t)K * (size_t)N : 0;
    const size_t brow = bexp + (size_t)bk * N + nbase;
    const char* gB = (const char*)(Bf + brow) + bnb;
    const size_t bstep = (size_t)KC * N * 2;

    const int nk = K / KC;

#define ISSUE_D(slot, kt)                                                       \
    do {                                                                        \
        uint32_t b_ = sb + (uint32_t)(slot) * STG;                              \
        size_t ak_ = (size_t)(kt) * 128;                                        \
        size_t bk_ = (size_t)(kt) * bstep;                                      \
        _Pragma("unroll")                                                       \
        for (int j_ = 0; j_ < 4; ++j_) {                                        \
            cp16(b_ + soA[j_],        gA + ak_ + j_ * 16);                      \
            cp16(b_ + OF_B + soB[j_], gB + bk_ + j_ * 16);                      \
        }                                                                       \
        CP_COMMIT();                                                            \
    } while (0)

    const int wm = (wid >> 2) * 64;
    const int wn = (wid & 3) * 32;

    uint32_t aOff[4];
#pragma unroll
    for (int mf = 0; mf < 4; ++mf)
        aOff[mf] = (uint32_t)(wm + mf * 16 + (lane & 15)) * 128u
                 + (uint32_t)((lane >> 4) * 16);
    uint32_t bB[2];
    {
        uint32_t r = lane & 7u, m = lane >> 3;
#pragma unroll
        for (int nf2 = 0; nf2 < 2; ++nf2) {
            uint32_t nb = (uint32_t)(wn + nf2 * 16 + (int)((m >> 1) * 8)) * 2u;
            bB[nf2] = ((m & 1u) * 8u + r) * 256u + (nb ^ (r << 4));
        }
    }

    float acc[4][4][4];
#pragma unroll
    for (int i = 0; i < 4; ++i)
#pragma unroll
        for (int j = 0; j < 4; ++j)
#pragma unroll
            for (int q = 0; q < 4; ++q) acc[i][j][q] = 0.f;

    ISSUE_D(0, 0);
    ISSUE_D(1, 1);

    for (int kt = 0; kt < nk; ++kt) {
        const int s = kt % 3;
        if (kt + 1 < nk) cp_wait<1>(); else cp_wait<0>();
        __syncthreads();
        if (kt + 2 < nk) ISSUE_D((kt + 2) % 3, kt + 2);

        const uint32_t stb = sb + (uint32_t)s * STG;
#pragma unroll
        for (int ks = 0; ks < 4; ++ks) {
            uint32_t a[4][4], b[2][4];
#pragma unroll
            for (int mf = 0; mf < 4; ++mf)
                ldsm4(a[mf], stb + swzA(aOff[mf] + ks * 32u));
#pragma unroll
            for (int nf2 = 0; nf2 < 2; ++nf2)
                ldsm4t(b[nf2], stb + OF_B + bB[nf2] + ks * 4096u);
#pragma unroll
            for (int mf = 0; mf < 4; ++mf)
#pragma unroll
                for (int nf = 0; nf < 4; ++nf)
                    mma_f16(acc[mf][nf], a[mf],
                            b[nf >> 1][(nf & 1) * 2], b[nf >> 1][(nf & 1) * 2 + 1]);
        }
    }
#undef ISSUE_D

    const size_t rowoff = ROUTED ? (size_t)seg : 0;
#pragma unroll
    for (int mf = 0; mf < 4; ++mf) {
#pragma unroll
        for (int nf = 0; nf < 4; ++nf) {
            int r0 = mbase + wm + mf * 16 + (lane >> 2);
            int n0 = nbase + wn + nf * 8 + (lane & 3) * 2;
            float* c = acc[mf][nf];
            if (r0 < M)
                *(float2*)&Cf[(rowoff + r0) * (size_t)N + n0] = make_float2(c[0], c[1]);
            if (r0 + 8 < M)
                *(float2*)&Cf[(rowoff + r0 + 8) * (size_t)N + n0] = make_float2(c[2], c[3]);
        }
    }
}

// ---------------- combine: out += w0*Y[slot0] + w1*Y[slot1] ------------------
__global__ void combine_kernel(float* __restrict__ out) {
    int t = blockIdx.y;
    int c = (blockIdx.x * blockDim.x + threadIdx.x) * 4;
    int s0 = g_slot[2 * t + 0], s1 = g_slot[2 * t + 1];
    float w0 = g_wgt[2 * t + 0], w1 = g_wgt[2 * t + 1];
    const float4 y0 = *(const float4*)&g_Y[(size_t)s0 * H_DIM + c];
    const float4 y1 = *(const float4*)&g_Y[(size_t)s1 * H_DIM + c];
    float4 o = *(float4*)&out[(size_t)t * H_DIM + c];
    o.x += w0 * y0.x + w1 * y1.x;
    o.y += w0 * y0.y + w1 * y1.y;
    o.z += w0 * y0.z + w1 * y1.z;
    o.w += w0 * y0.w + w1 * y1.w;
    *(float4*)&out[(size_t)t * H_DIM + c] = o;
}

// ---------------- launch -----------------------------------------------------
extern "C" void kernel_launch(void* const* d_in, const int* in_sizes, int n_in,
                              void* d_out, int out_size) {
    (void)in_sizes; (void)n_in; (void)out_size;
    const float* x      = (const float*)d_in[0];
    // d_in[1] router_w, d_in[2] router_b: dead inputs (RandomSTE forward = noise)
    const float* w_gate = (const float*)d_in[3];
    const float* w_up   = (const float*)d_in[4];
    const float* w_down = (const float*)d_in[5];
    const float* sg     = (const float*)d_in[6];
    const float* su     = (const float*)d_in[7];
    const float* sd     = (const float*)d_in[8];
    float* out = (float*)d_out;

    auto sym = [](const void* s) {
        void* p = nullptr;
        cudaGetSymbolAddress(&p, s);
        return p;
    };
    __half* xf  = (__half*)sym(g_xf);
    __half* sgf = (__half*)sym(g_sgf);
    __half* suf = (__half*)sym(g_suf);
    __half* sdf = (__half*)sym(g_sdf);
    __half* wgf = (__half*)sym(g_wgf);
    __half* wuf = (__half*)sym(g_wuf);
    __half* wdf = (__half*)sym(g_wdf);
    __half* hsf = (__half*)sym(g_hsf);
    __half* hrf = (__half*)sym(g_hrf);
    float*  Yp  = (float*)sym(g_Y);

    const int SM_F = 3 * 3 * (64 * 256);   // 147456
    const int SM_D = 3 * 2 * (64 * 256);   // 98304
    cudaFuncSetAttribute((const void*)mma_fused<false, false>,
                         cudaFuncAttributeMaxDynamicSharedMemorySize, SM_F);
    cudaFuncSetAttribute((const void*)mma_fused<true, true>,
                         cudaFuncAttributeMaxDynamicSharedMemorySize, SM_F);
    cudaFuncSetAttribute((const void*)mma_down<false>,
                         cudaFuncAttributeMaxDynamicSharedMemorySize, SM_D);
    cudaFuncSetAttribute((const void*)mma_down<true>,
                         cudaFuncAttributeMaxDynamicSharedMemorySize, SM_D);

    // Fork/join second stream (graph-capturable). Created per call; never
    // destroyed (kernel_launch runs only for correctness + capture; host-side
    // objects only — no device memory involved).
    cudaStream_t s2;
    cudaStreamCreateWithFlags(&s2, cudaStreamNonBlocking);
    cudaEvent_t evX, evR;
    cudaEventCreateWithFlags(&evX, cudaEventDisableTiming);
    cudaEventCreateWithFlags(&evR, cudaEventDisableTiming);

    // ---- legacy stream: x conversion, then fork marker
    conv_f16<<<(T_TOKENS * H_DIM) / 4096, 256>>>(x, xf);
    cudaEventRecord(evX, 0);

    // ---- stream 2: routing + expert weight conversions + routed GEMMs
    zero_kernel<<<1, 32, 0, s2>>>();
    route_kernel<<<T_TOKENS / 256, 256, 0, s2>>>();
    scan_kernel<<<1, 1, 0, s2>>>();
    scatter_kernel<<<T_TOKENS / 256, 256, 0, s2>>>();
    conv_f16<<<(E_NUM * H_DIM * I_DIM) / 4096, 256, 0, s2>>>(w_gate, wgf);
    conv_f16<<<(E_NUM * H_DIM * I_DIM) / 4096, 256, 0, s2>>>(w_up, wuf);
    conv_f16<<<(E_NUM * I_DIM * H_DIM) / 4096, 256, 0, s2>>>(w_down, wdf);
    cudaStreamWaitEvent(s2, evX, 0);   // routed GEMMs need xf
    mma_fused<true, true>
        <<<dim3(I_DIM / 128, SLOTS / 128, E_NUM), 256, SM_F, s2>>>(
            xf, wgf, wuf, hrf, H_DIM, I_DIM, 0);
    mma_down<true>
        <<<dim3(H_DIM / 128, SLOTS / 128, E_NUM), 256, SM_D, s2>>>(
            hrf, wdf, Yp, I_DIM, H_DIM, 0);
    cudaEventRecord(evR, s2);

    // ---- legacy stream: shared path
    conv_f16<<<(H_DIM * SI_DIM) / 4096, 256>>>(sg, sgf);
    conv_f16<<<(H_DIM * SI_DIM) / 4096, 256>>>(su, suf);
    conv_f16<<<(SI_DIM * H_DIM) / 4096, 256>>>(sd, sdf);
    mma_fused<false, false>
        <<<dim3(SI_DIM / 128, T_TOKENS / 128, 1), 256, SM_F>>>(
            xf, sgf, suf, hsf, H_DIM, SI_DIM, T_TOKENS);
    mma_down<false>
        <<<dim3(H_DIM / 128, T_TOKENS / 128, 1), 256, SM_D>>>(
            hsf, sdf, out, SI_DIM, H_DIM, T_TOKENS);

    // ---- join: combine needs routed Y (s2) and shared out (legacy)
    cudaStreamWaitEvent(0, evR, 0);
    combine_kernel<<<dim3(H_DIM / 1024, T_TOKENS), 256>>>(out);
}